// round 8
// baseline (speedup 1.0000x reference)
#include <cuda_runtime.h>
#include <cuda_bf16.h>
#include <cstddef>

// ---------------------------------------------------------------------------
// Scratch (device globals — no runtime allocation allowed)
// ---------------------------------------------------------------------------
__device__ float g_h  [4096 * 1024];   // LN output (reused for LN1 and LN2)
__device__ float g_qkv[4096 * 3072];   // QKV
__device__ float g_y  [4096 * 1024];   // attention output
__device__ float g_x1 [4096 * 1024];   // x + attn proj (residual 1)
__device__ float g_fc [4096 * 4096];   // FC (post-GELU)

// ---------------------------------------------------------------------------
// GELU (tanh approx), overflow-safe:  gelu(v) = v * (1 - 1/(e^{2u}+1))
// ---------------------------------------------------------------------------
__device__ __forceinline__ float gelu_tanh(float v) {
    float u = 0.7978845608028654f * fmaf(0.044715f * v * v, v, v);
    float e = __expf(2.0f * u);
    return v * (1.0f - 1.0f / (e + 1.0f));
}

// ---------------------------------------------------------------------------
// LayerNorm: one block per row of 1024, 256 threads, float4
// ---------------------------------------------------------------------------
__global__ void __launch_bounds__(256) ln_kernel(
    const float* __restrict__ x, const float* __restrict__ g,
    const float* __restrict__ b, float* __restrict__ o)
{
    const int row = blockIdx.x;
    const int tid = threadIdx.x;
    float4 v = reinterpret_cast<const float4*>(x + (size_t)row * 1024)[tid];
    float s  = v.x + v.y + v.z + v.w;
    float ss = v.x * v.x + v.y * v.y + v.z * v.z + v.w * v.w;
    #pragma unroll
    for (int off = 16; off; off >>= 1) {
        s  += __shfl_down_sync(0xffffffffu, s, off);
        ss += __shfl_down_sync(0xffffffffu, ss, off);
    }
    __shared__ float ws[8], wss[8];
    const int wid = tid >> 5, lane = tid & 31;
    if (lane == 0) { ws[wid] = s; wss[wid] = ss; }
    __syncthreads();
    s = 0.f; ss = 0.f;
    #pragma unroll
    for (int w = 0; w < 8; w++) { s += ws[w]; ss += wss[w]; }
    const float mean = s * (1.0f / 1024.0f);
    const float var  = ss * (1.0f / 1024.0f) - mean * mean;
    const float rstd = rsqrtf(var + 1e-5f);
    float4 gv = reinterpret_cast<const float4*>(g)[tid];
    float4 bv = reinterpret_cast<const float4*>(b)[tid];
    float4 r;
    r.x = (v.x - mean) * rstd * gv.x + bv.x;
    r.y = (v.y - mean) * rstd * gv.y + bv.y;
    r.z = (v.z - mean) * rstd * gv.z + bv.z;
    r.w = (v.w - mean) * rstd * gv.w + bv.w;
    reinterpret_cast<float4*>(o + (size_t)row * 1024)[tid] = r;
}

// ---------------------------------------------------------------------------
// SGEMM: C[M,N] = A[M,K] @ B[K,N] + bias (+Res / +GELU per EPI)
//   EPI 0: bias;  EPI 1: bias + residual;  EPI 2: bias + GELU
// 128x128x16 tile, 8x8 per thread, 256 threads, double-buffered SMEM with
// register prefetch. M,N,K assumed multiples of tile dims (true here).
// ---------------------------------------------------------------------------
template <int EPI>
__global__ void __launch_bounds__(256, 2) sgemm_kernel(
    const float* __restrict__ A, const float* __restrict__ B,
    const float* __restrict__ bias, const float* __restrict__ Res,
    float* __restrict__ C, int M, int N, int K)
{
    __shared__ float As[2][16][128];
    __shared__ float Bs[2][16][128];

    const int tid = threadIdx.x;
    const int block_row = blockIdx.y * 128;
    const int block_col = blockIdx.x * 128;
    const int trow = (tid >> 4) * 8;       // 0..120
    const int tcol = (tid & 15) * 8;       // 0..120

    // loader mappings
    const int a_r0 = tid >> 2;             // 0..63
    const int a_c0 = (tid & 3) * 4;        // 0,4,8,12
    const int b_r0 = tid >> 5;             // 0..7
    const int b_c0 = (tid & 31) * 4;       // 0..124

    const int nTiles = K >> 4;

    // prologue: tile 0 -> buffer 0
    {
        #pragma unroll
        for (int i = 0; i < 2; i++) {
            const int r = a_r0 + i * 64;
            float4 av = *reinterpret_cast<const float4*>(
                A + (size_t)(block_row + r) * K + a_c0);
            As[0][a_c0 + 0][r] = av.x;
            As[0][a_c0 + 1][r] = av.y;
            As[0][a_c0 + 2][r] = av.z;
            As[0][a_c0 + 3][r] = av.w;
        }
        #pragma unroll
        for (int i = 0; i < 2; i++) {
            const int r = b_r0 + i * 8;
            float4 bv = *reinterpret_cast<const float4*>(
                B + (size_t)r * N + block_col + b_c0);
            *reinterpret_cast<float4*>(&Bs[0][r][b_c0]) = bv;
        }
    }
    __syncthreads();

    float acc[8][8];
    #pragma unroll
    for (int i = 0; i < 8; i++)
        #pragma unroll
        for (int j = 0; j < 8; j++) acc[i][j] = 0.f;

    for (int t = 0; t < nTiles; t++) {
        const int cur = t & 1, nxt = cur ^ 1;
        float4 aReg[2], bReg[2];
        const bool has = (t + 1 < nTiles);
        if (has) {
            const int k0 = (t + 1) << 4;
            #pragma unroll
            for (int i = 0; i < 2; i++) {
                aReg[i] = *reinterpret_cast<const float4*>(
                    A + (size_t)(block_row + a_r0 + i * 64) * K + k0 + a_c0);
                bReg[i] = *reinterpret_cast<const float4*>(
                    B + (size_t)(k0 + b_r0 + i * 8) * N + block_col + b_c0);
            }
        }

        #pragma unroll
        for (int k = 0; k < 16; k++) {
            float4 a0 = *reinterpret_cast<const float4*>(&As[cur][k][trow]);
            float4 a1 = *reinterpret_cast<const float4*>(&As[cur][k][trow + 4]);
            float4 b0 = *reinterpret_cast<const float4*>(&Bs[cur][k][tcol]);
            float4 b1 = *reinterpret_cast<const float4*>(&Bs[cur][k][tcol + 4]);
            const float af[8] = {a0.x, a0.y, a0.z, a0.w, a1.x, a1.y, a1.z, a1.w};
            const float bf[8] = {b0.x, b0.y, b0.z, b0.w, b1.x, b1.y, b1.z, b1.w};
            #pragma unroll
            for (int i = 0; i < 8; i++)
                #pragma unroll
                for (int j = 0; j < 8; j++)
                    acc[i][j] = fmaf(af[i], bf[j], acc[i][j]);
        }

        if (has) {
            #pragma unroll
            for (int i = 0; i < 2; i++) {
                const int r = a_r0 + i * 64;
                As[nxt][a_c0 + 0][r] = aReg[i].x;
                As[nxt][a_c0 + 1][r] = aReg[i].y;
                As[nxt][a_c0 + 2][r] = aReg[i].z;
                As[nxt][a_c0 + 3][r] = aReg[i].w;
                *reinterpret_cast<float4*>(&Bs[nxt][b_r0 + i * 8][b_c0]) = bReg[i];
            }
        }
        __syncthreads();
    }

    // epilogue
    #pragma unroll
    for (int i = 0; i < 8; i++) {
        const int row = block_row + trow + i;
        #pragma unroll
        for (int j4 = 0; j4 < 2; j4++) {
            const int col = block_col + tcol + j4 * 4;
            float4 v;
            v.x = acc[i][j4 * 4 + 0] + bias[col + 0];
            v.y = acc[i][j4 * 4 + 1] + bias[col + 1];
            v.z = acc[i][j4 * 4 + 2] + bias[col + 2];
            v.w = acc[i][j4 * 4 + 3] + bias[col + 3];
            if (EPI == 1) {
                float4 r = *reinterpret_cast<const float4*>(
                    Res + (size_t)row * N + col);
                v.x += r.x; v.y += r.y; v.z += r.z; v.w += r.w;
            }
            if (EPI == 2) {
                v.x = gelu_tanh(v.x); v.y = gelu_tanh(v.y);
                v.z = gelu_tanh(v.z); v.w = gelu_tanh(v.w);
            }
            *reinterpret_cast<float4*>(C + (size_t)row * N + col) = v;
        }
    }
}

// ---------------------------------------------------------------------------
// Flash attention (fp32, causal): 64x64 Q/KV tiles, online softmax.
// grid = (T/64, B*H), 256 threads. qkv layout [B,T,3C], head h at cols h*64.
// Dynamic SMEM = 67584 bytes.
// ---------------------------------------------------------------------------
__global__ void __launch_bounds__(256) attn_kernel(
    const float* __restrict__ qkv, float* __restrict__ y)
{
    const int T = 2048, C3 = 3072;
    extern __shared__ float sm[];
    float* Qs   = sm;                 // [64][64]
    float* KsT  = Qs  + 64 * 64;      // [64 d][68]  (d-major, padded)
    float* Vs   = KsT + 64 * 68;      // [64][64]
    float* Ss   = Vs  + 64 * 64;      // [64][65]    (padded)
    float* m_s  = Ss  + 64 * 65;      // [64]
    float* l_s  = m_s + 64;           // [64]
    float* al_s = l_s + 64;           // [64]

    const int q0 = blockIdx.x * 64;
    const int bh = blockIdx.y;
    const int bb = bh >> 4, hh = bh & 15;
    const float* qbase = qkv + (size_t)bb * T * C3 + hh * 64;
    const float* kbase = qbase + 1024;
    const float* vbase = qbase + 2048;

    const int tid = threadIdx.x;
    const int tx = tid & 15, ty = tid >> 4;
    const int r0 = ty * 4, c0 = tx * 4;

    // load Q (scaled by 1/sqrt(64))
    #pragma unroll
    for (int i = 0; i < 4; i++) {
        const int v = tid + i * 256;
        const int r = v >> 4, d4 = (v & 15) * 4;
        float4 q = *reinterpret_cast<const float4*>(
            qbase + (size_t)(q0 + r) * C3 + d4);
        q.x *= 0.125f; q.y *= 0.125f; q.z *= 0.125f; q.w *= 0.125f;
        *reinterpret_cast<float4*>(Qs + r * 64 + d4) = q;
    }
    if (tid < 64) { m_s[tid] = -1e30f; l_s[tid] = 0.f; }

    float o[4][4];
    #pragma unroll
    for (int i = 0; i < 4; i++)
        #pragma unroll
        for (int j = 0; j < 4; j++) o[i][j] = 0.f;

    const int ntiles = (q0 >> 6) + 1;
    for (int jt = 0; jt < ntiles; jt++) {
        const int j0 = jt * 64;
        __syncthreads();
        // K -> KsT[d][j] (lanes walk j: conflict-free SMEM stores)
        #pragma unroll
        for (int i = 0; i < 4; i++) {
            const int v = tid + i * 256;
            const int jr = v & 63, d4 = (v >> 6) * 4;
            float4 kk = *reinterpret_cast<const float4*>(
                kbase + (size_t)(j0 + jr) * C3 + d4);
            KsT[(d4 + 0) * 68 + jr] = kk.x;
            KsT[(d4 + 1) * 68 + jr] = kk.y;
            KsT[(d4 + 2) * 68 + jr] = kk.z;
            KsT[(d4 + 3) * 68 + jr] = kk.w;
        }
        // V straight (coalesced global, conflict-free stores)
        #pragma unroll
        for (int i = 0; i < 4; i++) {
            const int v = tid + i * 256;
            const int jr = v >> 4, d4 = (v & 15) * 4;
            float4 vv = *reinterpret_cast<const float4*>(
                vbase + (size_t)(j0 + jr) * C3 + d4);
            *reinterpret_cast<float4*>(Vs + jr * 64 + d4) = vv;
        }
        __syncthreads();

        // S = Q K^T (4x4 per thread)
        float s4[4][4];
        #pragma unroll
        for (int i = 0; i < 4; i++)
            #pragma unroll
            for (int j = 0; j < 4; j++) s4[i][j] = 0.f;
        #pragma unroll 8
        for (int d = 0; d < 64; d++) {
            const float4 kv = *reinterpret_cast<const float4*>(KsT + d * 68 + c0);
            const float q0v = Qs[(r0 + 0) * 64 + d];
            const float q1v = Qs[(r0 + 1) * 64 + d];
            const float q2v = Qs[(r0 + 2) * 64 + d];
            const float q3v = Qs[(r0 + 3) * 64 + d];
            s4[0][0] = fmaf(q0v, kv.x, s4[0][0]); s4[0][1] = fmaf(q0v, kv.y, s4[0][1]);
            s4[0][2] = fmaf(q0v, kv.z, s4[0][2]); s4[0][3] = fmaf(q0v, kv.w, s4[0][3]);
            s4[1][0] = fmaf(q1v, kv.x, s4[1][0]); s4[1][1] = fmaf(q1v, kv.y, s4[1][1]);
            s4[1][2] = fmaf(q1v, kv.z, s4[1][2]); s4[1][3] = fmaf(q1v, kv.w, s4[1][3]);
            s4[2][0] = fmaf(q2v, kv.x, s4[2][0]); s4[2][1] = fmaf(q2v, kv.y, s4[2][1]);
            s4[2][2] = fmaf(q2v, kv.z, s4[2][2]); s4[2][3] = fmaf(q2v, kv.w, s4[2][3]);
            s4[3][0] = fmaf(q3v, kv.x, s4[3][0]); s4[3][1] = fmaf(q3v, kv.y, s4[3][1]);
            s4[3][2] = fmaf(q3v, kv.z, s4[3][2]); s4[3][3] = fmaf(q3v, kv.w, s4[3][3]);
        }
        // causal mask on diagonal tile
        if (j0 == q0) {
            #pragma unroll
            for (int rr = 0; rr < 4; rr++)
                #pragma unroll
                for (int cc = 0; cc < 4; cc++)
                    if (c0 + cc > r0 + rr) s4[rr][cc] = -1e30f;
        }
        #pragma unroll
        for (int rr = 0; rr < 4; rr++)
            #pragma unroll
            for (int cc = 0; cc < 4; cc++)
                Ss[(r0 + rr) * 65 + c0 + cc] = s4[rr][cc];
        __syncthreads();

        // online softmax stats: 4 threads per row
        {
            const int row = tid >> 2, part = tid & 3;
            float* srow = Ss + row * 65 + part * 16;
            float mx = -1e30f;
            #pragma unroll
            for (int j = 0; j < 16; j++) mx = fmaxf(mx, srow[j]);
            mx = fmaxf(mx, __shfl_xor_sync(0xffffffffu, mx, 1));
            mx = fmaxf(mx, __shfl_xor_sync(0xffffffffu, mx, 2));
            const float m_old = m_s[row];
            const float m_new = fmaxf(m_old, mx);
            float sum = 0.f;
            #pragma unroll
            for (int j = 0; j < 16; j++) {
                const float p = __expf(srow[j] - m_new);
                srow[j] = p;
                sum += p;
            }
            sum += __shfl_xor_sync(0xffffffffu, sum, 1);
            sum += __shfl_xor_sync(0xffffffffu, sum, 2);
            if (part == 0) {
                const float alpha = __expf(m_old - m_new);
                al_s[row] = alpha;
                m_s[row]  = m_new;
                l_s[row]  = l_s[row] * alpha + sum;
            }
        }
        __syncthreads();

        // O = O*alpha + P @ V
        const float a0 = al_s[r0 + 0], a1 = al_s[r0 + 1];
        const float a2 = al_s[r0 + 2], a3 = al_s[r0 + 3];
        #pragma unroll
        for (int cc = 0; cc < 4; cc++) {
            o[0][cc] *= a0; o[1][cc] *= a1; o[2][cc] *= a2; o[3][cc] *= a3;
        }
        #pragma unroll 8
        for (int j = 0; j < 64; j++) {
            const float4 vv = *reinterpret_cast<const float4*>(Vs + j * 64 + c0);
            const float p0 = Ss[(r0 + 0) * 65 + j];
            const float p1 = Ss[(r0 + 1) * 65 + j];
            const float p2 = Ss[(r0 + 2) * 65 + j];
            const float p3 = Ss[(r0 + 3) * 65 + j];
            o[0][0] = fmaf(p0, vv.x, o[0][0]); o[0][1] = fmaf(p0, vv.y, o[0][1]);
            o[0][2] = fmaf(p0, vv.z, o[0][2]); o[0][3] = fmaf(p0, vv.w, o[0][3]);
            o[1][0] = fmaf(p1, vv.x, o[1][0]); o[1][1] = fmaf(p1, vv.y, o[1][1]);
            o[1][2] = fmaf(p1, vv.z, o[1][2]); o[1][3] = fmaf(p1, vv.w, o[1][3]);
            o[2][0] = fmaf(p2, vv.x, o[2][0]); o[2][1] = fmaf(p2, vv.y, o[2][1]);
            o[2][2] = fmaf(p2, vv.z, o[2][2]); o[2][3] = fmaf(p2, vv.w, o[2][3]);
            o[3][0] = fmaf(p3, vv.x, o[3][0]); o[3][1] = fmaf(p3, vv.y, o[3][1]);
            o[3][2] = fmaf(p3, vv.z, o[3][2]); o[3][3] = fmaf(p3, vv.w, o[3][3]);
        }
    }

    // finalize and write y[B,T,C]
    #pragma unroll
    for (int rr = 0; rr < 4; rr++) {
        const float inv = 1.0f / l_s[r0 + rr];
        float4 ov = make_float4(o[rr][0] * inv, o[rr][1] * inv,
                                o[rr][2] * inv, o[rr][3] * inv);
        *reinterpret_cast<float4*>(
            y + ((size_t)bb * T + q0 + r0 + rr) * 1024 + hh * 64 + c0) = ov;
    }
}

// ---------------------------------------------------------------------------
// Launch
// ---------------------------------------------------------------------------
extern "C" void kernel_launch(void* const* d_in, const int* in_sizes, int n_in,
                              void* d_out, int out_size)
{
    const float* x      = (const float*)d_in[0];
    const float* ln1_g  = (const float*)d_in[1];
    const float* ln1_b  = (const float*)d_in[2];
    const float* W_attn = (const float*)d_in[3];
    const float* b_attn = (const float*)d_in[4];
    const float* W_o    = (const float*)d_in[5];
    const float* b_o    = (const float*)d_in[6];
    const float* ln2_g  = (const float*)d_in[7];
    const float* ln2_b  = (const float*)d_in[8];
    const float* W_fc   = (const float*)d_in[9];
    const float* b_fc   = (const float*)d_in[10];
    const float* W_fc2  = (const float*)d_in[11];
    const float* b_fc2  = (const float*)d_in[12];
    float* out = (float*)d_out;

    float *h, *qkv, *yb, *x1, *fc;
    cudaGetSymbolAddress((void**)&h,   g_h);
    cudaGetSymbolAddress((void**)&qkv, g_qkv);
    cudaGetSymbolAddress((void**)&yb,  g_y);
    cudaGetSymbolAddress((void**)&x1,  g_x1);
    cudaGetSymbolAddress((void**)&fc,  g_fc);

    const int ATTN_SMEM = 67584;
    cudaFuncSetAttribute(attn_kernel,
                         cudaFuncAttributeMaxDynamicSharedMemorySize, ATTN_SMEM);

    const int M = 4096;  // B*T

    // 1. LN1
    ln_kernel<<<M, 256>>>(x, ln1_g, ln1_b, h);
    // 2. QKV = h @ W_attn + b_attn   [4096, 3072]
    sgemm_kernel<0><<<dim3(3072 / 128, M / 128), 256>>>(
        h, W_attn, b_attn, nullptr, qkv, M, 3072, 1024);
    // 3. attention -> y [4096, 1024]
    attn_kernel<<<dim3(32, 32), 256, ATTN_SMEM>>>(qkv, yb);
    // 4. x1 = x + y @ W_o + b_o
    sgemm_kernel<1><<<dim3(1024 / 128, M / 128), 256>>>(
        yb, W_o, b_o, x, x1, M, 1024, 1024);
    // 5. LN2
    ln_kernel<<<M, 256>>>(x1, ln2_g, ln2_b, h);
    // 6. fc = gelu(h @ W_fc + b_fc)  [4096, 4096]
    sgemm_kernel<2><<<dim3(4096 / 128, M / 128), 256>>>(
        h, W_fc, b_fc, nullptr, fc, M, 4096, 1024);
    // 7. out = x1 + fc @ W_fc2 + b_fc2
    sgemm_kernel<1><<<dim3(1024 / 128, M / 128), 256>>>(
        fc, W_fc2, b_fc2, x1, out, M, 1024, 4096);
}

// round 9
// speedup vs baseline: 1.0027x; 1.0027x over previous
#include <cuda_runtime.h>
#include <cuda_bf16.h>
#include <cstddef>

// ---------------------------------------------------------------------------
// Scratch (device globals — no runtime allocation allowed)
// ---------------------------------------------------------------------------
__device__ float g_h  [4096 * 1024];   // LN output (reused for LN1 and LN2)
__device__ float g_qkv[4096 * 3072];   // QKV
__device__ float g_y  [4096 * 1024];   // attention output
__device__ float g_x1 [4096 * 1024];   // x + attn proj (residual 1)
__device__ float g_fc [4096 * 4096];   // FC (post-GELU)

// ---------------------------------------------------------------------------
// GELU (tanh approx), overflow-safe:  gelu(v) = v * (1 - 1/(e^{2u}+1))
// ---------------------------------------------------------------------------
__device__ __forceinline__ float gelu_tanh(float v) {
    float u = 0.7978845608028654f * fmaf(0.044715f * v * v, v, v);
    float e = __expf(2.0f * u);
    return v * (1.0f - 1.0f / (e + 1.0f));
}

// ---------------------------------------------------------------------------
// LayerNorm: one block per row of 1024, 256 threads, float4
// ---------------------------------------------------------------------------
__global__ void __launch_bounds__(256) ln_kernel(
    const float* __restrict__ x, const float* __restrict__ g,
    const float* __restrict__ b, float* __restrict__ o)
{
    const int row = blockIdx.x;
    const int tid = threadIdx.x;
    float4 v = reinterpret_cast<const float4*>(x + (size_t)row * 1024)[tid];
    float s  = v.x + v.y + v.z + v.w;
    float ss = v.x * v.x + v.y * v.y + v.z * v.z + v.w * v.w;
    #pragma unroll
    for (int off = 16; off; off >>= 1) {
        s  += __shfl_down_sync(0xffffffffu, s, off);
        ss += __shfl_down_sync(0xffffffffu, ss, off);
    }
    __shared__ float ws[8], wss[8];
    const int wid = tid >> 5, lane = tid & 31;
    if (lane == 0) { ws[wid] = s; wss[wid] = ss; }
    __syncthreads();
    s = 0.f; ss = 0.f;
    #pragma unroll
    for (int w = 0; w < 8; w++) { s += ws[w]; ss += wss[w]; }
    const float mean = s * (1.0f / 1024.0f);
    const float var  = ss * (1.0f / 1024.0f) - mean * mean;
    const float rstd = rsqrtf(var + 1e-5f);
    float4 gv = reinterpret_cast<const float4*>(g)[tid];
    float4 bv = reinterpret_cast<const float4*>(b)[tid];
    float4 r;
    r.x = (v.x - mean) * rstd * gv.x + bv.x;
    r.y = (v.y - mean) * rstd * gv.y + bv.y;
    r.z = (v.z - mean) * rstd * gv.z + bv.z;
    r.w = (v.w - mean) * rstd * gv.w + bv.w;
    reinterpret_cast<float4*>(o + (size_t)row * 1024)[tid] = r;
}

// ---------------------------------------------------------------------------
// SGEMM: C[M,N] = A[M,K] @ B[K,N] + bias (+Res / +GELU per EPI)
//   EPI 0: bias;  EPI 1: bias + residual;  EPI 2: bias + GELU
// 128x128x16 tile, 8x8 per thread, 256 threads, double-buffered SMEM with
// register prefetch. M,N,K assumed multiples of tile dims (true here).
// ---------------------------------------------------------------------------
template <int EPI>
__global__ void __launch_bounds__(256, 2) sgemm_kernel(
    const float* __restrict__ A, const float* __restrict__ B,
    const float* __restrict__ bias, const float* __restrict__ Res,
    float* __restrict__ C, int M, int N, int K)
{
    __shared__ float As[2][16][128];
    __shared__ float Bs[2][16][128];

    const int tid = threadIdx.x;
    const int block_row = blockIdx.y * 128;
    const int block_col = blockIdx.x * 128;
    const int trow = (tid >> 4) * 8;       // 0..120
    const int tcol = (tid & 15) * 8;       // 0..120

    // loader mappings
    const int a_r0 = tid >> 2;             // 0..63
    const int a_c0 = (tid & 3) * 4;        // 0,4,8,12
    const int b_r0 = tid >> 5;             // 0..7
    const int b_c0 = (tid & 31) * 4;       // 0..124

    const int nTiles = K >> 4;

    // prologue: tile 0 -> buffer 0
    {
        #pragma unroll
        for (int i = 0; i < 2; i++) {
            const int r = a_r0 + i * 64;
            float4 av = *reinterpret_cast<const float4*>(
                A + (size_t)(block_row + r) * K + a_c0);
            As[0][a_c0 + 0][r] = av.x;
            As[0][a_c0 + 1][r] = av.y;
            As[0][a_c0 + 2][r] = av.z;
            As[0][a_c0 + 3][r] = av.w;
        }
        #pragma unroll
        for (int i = 0; i < 2; i++) {
            const int r = b_r0 + i * 8;
            float4 bv = *reinterpret_cast<const float4*>(
                B + (size_t)r * N + block_col + b_c0);
            *reinterpret_cast<float4*>(&Bs[0][r][b_c0]) = bv;
        }
    }
    __syncthreads();

    float acc[8][8];
    #pragma unroll
    for (int i = 0; i < 8; i++)
        #pragma unroll
        for (int j = 0; j < 8; j++) acc[i][j] = 0.f;

    for (int t = 0; t < nTiles; t++) {
        const int cur = t & 1, nxt = cur ^ 1;
        float4 aReg[2], bReg[2];
        const bool has = (t + 1 < nTiles);
        if (has) {
            const int k0 = (t + 1) << 4;
            #pragma unroll
            for (int i = 0; i < 2; i++) {
                aReg[i] = *reinterpret_cast<const float4*>(
                    A + (size_t)(block_row + a_r0 + i * 64) * K + k0 + a_c0);
                bReg[i] = *reinterpret_cast<const float4*>(
                    B + (size_t)(k0 + b_r0 + i * 8) * N + block_col + b_c0);
            }
        }

        #pragma unroll
        for (int k = 0; k < 16; k++) {
            float4 a0 = *reinterpret_cast<const float4*>(&As[cur][k][trow]);
            float4 a1 = *reinterpret_cast<const float4*>(&As[cur][k][trow + 4]);
            float4 b0 = *reinterpret_cast<const float4*>(&Bs[cur][k][tcol]);
            float4 b1 = *reinterpret_cast<const float4*>(&Bs[cur][k][tcol + 4]);
            const float af[8] = {a0.x, a0.y, a0.z, a0.w, a1.x, a1.y, a1.z, a1.w};
            const float bf[8] = {b0.x, b0.y, b0.z, b0.w, b1.x, b1.y, b1.z, b1.w};
            #pragma unroll
            for (int i = 0; i < 8; i++)
                #pragma unroll
                for (int j = 0; j < 8; j++)
                    acc[i][j] = fmaf(af[i], bf[j], acc[i][j]);
        }

        if (has) {
            #pragma unroll
            for (int i = 0; i < 2; i++) {
                const int r = a_r0 + i * 64;
                As[nxt][a_c0 + 0][r] = aReg[i].x;
                As[nxt][a_c0 + 1][r] = aReg[i].y;
                As[nxt][a_c0 + 2][r] = aReg[i].z;
                As[nxt][a_c0 + 3][r] = aReg[i].w;
                *reinterpret_cast<float4*>(&Bs[nxt][b_r0 + i * 8][b_c0]) = bReg[i];
            }
        }
        __syncthreads();
    }

    // epilogue
    #pragma unroll
    for (int i = 0; i < 8; i++) {
        const int row = block_row + trow + i;
        #pragma unroll
        for (int j4 = 0; j4 < 2; j4++) {
            const int col = block_col + tcol + j4 * 4;
            float4 v;
            v.x = acc[i][j4 * 4 + 0] + bias[col + 0];
            v.y = acc[i][j4 * 4 + 1] + bias[col + 1];
            v.z = acc[i][j4 * 4 + 2] + bias[col + 2];
            v.w = acc[i][j4 * 4 + 3] + bias[col + 3];
            if (EPI == 1) {
                float4 r = *reinterpret_cast<const float4*>(
                    Res + (size_t)row * N + col);
                v.x += r.x; v.y += r.y; v.z += r.z; v.w += r.w;
            }
            if (EPI == 2) {
                v.x = gelu_tanh(v.x); v.y = gelu_tanh(v.y);
                v.z = gelu_tanh(v.z); v.w = gelu_tanh(v.w);
            }
            *reinterpret_cast<float4*>(C + (size_t)row * N + col) = v;
        }
    }
}

// ---------------------------------------------------------------------------
// Flash attention (fp32, causal): 64x64 Q/KV tiles, online softmax.
// grid = (T/64, B*H), 256 threads. qkv layout [B,T,3C], head h at cols h*64.
// Dynamic SMEM = 67584 bytes.
// ---------------------------------------------------------------------------
__global__ void __launch_bounds__(256) attn_kernel(
    const float* __restrict__ qkv, float* __restrict__ y)
{
    const int T = 2048, C3 = 3072;
    extern __shared__ float sm[];
    float* Qs   = sm;                 // [64][64]
    float* KsT  = Qs  + 64 * 64;      // [64 d][68]  (d-major, padded)
    float* Vs   = KsT + 64 * 68;      // [64][64]
    float* Ss   = Vs  + 64 * 64;      // [64][65]    (padded)
    float* m_s  = Ss  + 64 * 65;      // [64]
    float* l_s  = m_s + 64;           // [64]
    float* al_s = l_s + 64;           // [64]

    const int q0 = blockIdx.x * 64;
    const int bh = blockIdx.y;
    const int bb = bh >> 4, hh = bh & 15;
    const float* qbase = qkv + (size_t)bb * T * C3 + hh * 64;
    const float* kbase = qbase + 1024;
    const float* vbase = qbase + 2048;

    const int tid = threadIdx.x;
    const int tx = tid & 15, ty = tid >> 4;
    const int r0 = ty * 4, c0 = tx * 4;

    // load Q (scaled by 1/sqrt(64))
    #pragma unroll
    for (int i = 0; i < 4; i++) {
        const int v = tid + i * 256;
        const int r = v >> 4, d4 = (v & 15) * 4;
        float4 q = *reinterpret_cast<const float4*>(
            qbase + (size_t)(q0 + r) * C3 + d4);
        q.x *= 0.125f; q.y *= 0.125f; q.z *= 0.125f; q.w *= 0.125f;
        *reinterpret_cast<float4*>(Qs + r * 64 + d4) = q;
    }
    if (tid < 64) { m_s[tid] = -1e30f; l_s[tid] = 0.f; }

    float o[4][4];
    #pragma unroll
    for (int i = 0; i < 4; i++)
        #pragma unroll
        for (int j = 0; j < 4; j++) o[i][j] = 0.f;

    const int ntiles = (q0 >> 6) + 1;
    for (int jt = 0; jt < ntiles; jt++) {
        const int j0 = jt * 64;
        __syncthreads();
        // K -> KsT[d][j] (lanes walk j: conflict-free SMEM stores)
        #pragma unroll
        for (int i = 0; i < 4; i++) {
            const int v = tid + i * 256;
            const int jr = v & 63, d4 = (v >> 6) * 4;
            float4 kk = *reinterpret_cast<const float4*>(
                kbase + (size_t)(j0 + jr) * C3 + d4);
            KsT[(d4 + 0) * 68 + jr] = kk.x;
            KsT[(d4 + 1) * 68 + jr] = kk.y;
            KsT[(d4 + 2) * 68 + jr] = kk.z;
            KsT[(d4 + 3) * 68 + jr] = kk.w;
        }
        // V straight (coalesced global, conflict-free stores)
        #pragma unroll
        for (int i = 0; i < 4; i++) {
            const int v = tid + i * 256;
            const int jr = v >> 4, d4 = (v & 15) * 4;
            float4 vv = *reinterpret_cast<const float4*>(
                vbase + (size_t)(j0 + jr) * C3 + d4);
            *reinterpret_cast<float4*>(Vs + jr * 64 + d4) = vv;
        }
        __syncthreads();

        // S = Q K^T (4x4 per thread)
        float s4[4][4];
        #pragma unroll
        for (int i = 0; i < 4; i++)
            #pragma unroll
            for (int j = 0; j < 4; j++) s4[i][j] = 0.f;
        #pragma unroll 8
        for (int d = 0; d < 64; d++) {
            const float4 kv = *reinterpret_cast<const float4*>(KsT + d * 68 + c0);
            const float q0v = Qs[(r0 + 0) * 64 + d];
            const float q1v = Qs[(r0 + 1) * 64 + d];
            const float q2v = Qs[(r0 + 2) * 64 + d];
            const float q3v = Qs[(r0 + 3) * 64 + d];
            s4[0][0] = fmaf(q0v, kv.x, s4[0][0]); s4[0][1] = fmaf(q0v, kv.y, s4[0][1]);
            s4[0][2] = fmaf(q0v, kv.z, s4[0][2]); s4[0][3] = fmaf(q0v, kv.w, s4[0][3]);
            s4[1][0] = fmaf(q1v, kv.x, s4[1][0]); s4[1][1] = fmaf(q1v, kv.y, s4[1][1]);
            s4[1][2] = fmaf(q1v, kv.z, s4[1][2]); s4[1][3] = fmaf(q1v, kv.w, s4[1][3]);
            s4[2][0] = fmaf(q2v, kv.x, s4[2][0]); s4[2][1] = fmaf(q2v, kv.y, s4[2][1]);
            s4[2][2] = fmaf(q2v, kv.z, s4[2][2]); s4[2][3] = fmaf(q2v, kv.w, s4[2][3]);
            s4[3][0] = fmaf(q3v, kv.x, s4[3][0]); s4[3][1] = fmaf(q3v, kv.y, s4[3][1]);
            s4[3][2] = fmaf(q3v, kv.z, s4[3][2]); s4[3][3] = fmaf(q3v, kv.w, s4[3][3]);
        }
        // causal mask on diagonal tile
        if (j0 == q0) {
            #pragma unroll
            for (int rr = 0; rr < 4; rr++)
                #pragma unroll
                for (int cc = 0; cc < 4; cc++)
                    if (c0 + cc > r0 + rr) s4[rr][cc] = -1e30f;
        }
        #pragma unroll
        for (int rr = 0; rr < 4; rr++)
            #pragma unroll
            for (int cc = 0; cc < 4; cc++)
                Ss[(r0 + rr) * 65 + c0 + cc] = s4[rr][cc];
        __syncthreads();

        // online softmax stats: 4 threads per row
        {
            const int row = tid >> 2, part = tid & 3;
            float* srow = Ss + row * 65 + part * 16;
            float mx = -1e30f;
            #pragma unroll
            for (int j = 0; j < 16; j++) mx = fmaxf(mx, srow[j]);
            mx = fmaxf(mx, __shfl_xor_sync(0xffffffffu, mx, 1));
            mx = fmaxf(mx, __shfl_xor_sync(0xffffffffu, mx, 2));
            const float m_old = m_s[row];
            const float m_new = fmaxf(m_old, mx);
            float sum = 0.f;
            #pragma unroll
            for (int j = 0; j < 16; j++) {
                const float p = __expf(srow[j] - m_new);
                srow[j] = p;
                sum += p;
            }
            sum += __shfl_xor_sync(0xffffffffu, sum, 1);
            sum += __shfl_xor_sync(0xffffffffu, sum, 2);
            if (part == 0) {
                const float alpha = __expf(m_old - m_new);
                al_s[row] = alpha;
                m_s[row]  = m_new;
                l_s[row]  = l_s[row] * alpha + sum;
            }
        }
        __syncthreads();

        // O = O*alpha + P @ V
        const float a0 = al_s[r0 + 0], a1 = al_s[r0 + 1];
        const float a2 = al_s[r0 + 2], a3 = al_s[r0 + 3];
        #pragma unroll
        for (int cc = 0; cc < 4; cc++) {
            o[0][cc] *= a0; o[1][cc] *= a1; o[2][cc] *= a2; o[3][cc] *= a3;
        }
        #pragma unroll 8
        for (int j = 0; j < 64; j++) {
            const float4 vv = *reinterpret_cast<const float4*>(Vs + j * 64 + c0);
            const float p0 = Ss[(r0 + 0) * 65 + j];
            const float p1 = Ss[(r0 + 1) * 65 + j];
            const float p2 = Ss[(r0 + 2) * 65 + j];
            const float p3 = Ss[(r0 + 3) * 65 + j];
            o[0][0] = fmaf(p0, vv.x, o[0][0]); o[0][1] = fmaf(p0, vv.y, o[0][1]);
            o[0][2] = fmaf(p0, vv.z, o[0][2]); o[0][3] = fmaf(p0, vv.w, o[0][3]);
            o[1][0] = fmaf(p1, vv.x, o[1][0]); o[1][1] = fmaf(p1, vv.y, o[1][1]);
            o[1][2] = fmaf(p1, vv.z, o[1][2]); o[1][3] = fmaf(p1, vv.w, o[1][3]);
            o[2][0] = fmaf(p2, vv.x, o[2][0]); o[2][1] = fmaf(p2, vv.y, o[2][1]);
            o[2][2] = fmaf(p2, vv.z, o[2][2]); o[2][3] = fmaf(p2, vv.w, o[2][3]);
            o[3][0] = fmaf(p3, vv.x, o[3][0]); o[3][1] = fmaf(p3, vv.y, o[3][1]);
            o[3][2] = fmaf(p3, vv.z, o[3][2]); o[3][3] = fmaf(p3, vv.w, o[3][3]);
        }
    }

    // finalize and write y[B,T,C]
    #pragma unroll
    for (int rr = 0; rr < 4; rr++) {
        const float inv = 1.0f / l_s[r0 + rr];
        float4 ov = make_float4(o[rr][0] * inv, o[rr][1] * inv,
                                o[rr][2] * inv, o[rr][3] * inv);
        *reinterpret_cast<float4*>(
            y + ((size_t)bb * T + q0 + r0 + rr) * 1024 + hh * 64 + c0) = ov;
    }
}

// ---------------------------------------------------------------------------
// Launch
// ---------------------------------------------------------------------------
extern "C" void kernel_launch(void* const* d_in, const int* in_sizes, int n_in,
                              void* d_out, int out_size)
{
    const float* x      = (const float*)d_in[0];
    const float* ln1_g  = (const float*)d_in[1];
    const float* ln1_b  = (const float*)d_in[2];
    const float* W_attn = (const float*)d_in[3];
    const float* b_attn = (const float*)d_in[4];
    const float* W_o    = (const float*)d_in[5];
    const float* b_o    = (const float*)d_in[6];
    const float* ln2_g  = (const float*)d_in[7];
    const float* ln2_b  = (const float*)d_in[8];
    const float* W_fc   = (const float*)d_in[9];
    const float* b_fc   = (const float*)d_in[10];
    const float* W_fc2  = (const float*)d_in[11];
    const float* b_fc2  = (const float*)d_in[12];
    float* out = (float*)d_out;

    float *h, *qkv, *yb, *x1, *fc;
    cudaGetSymbolAddress((void**)&h,   g_h);
    cudaGetSymbolAddress((void**)&qkv, g_qkv);
    cudaGetSymbolAddress((void**)&yb,  g_y);
    cudaGetSymbolAddress((void**)&x1,  g_x1);
    cudaGetSymbolAddress((void**)&fc,  g_fc);

    const int ATTN_SMEM = 67584;
    cudaFuncSetAttribute(attn_kernel,
                         cudaFuncAttributeMaxDynamicSharedMemorySize, ATTN_SMEM);

    const int M = 4096;  // B*T

    // 1. LN1
    ln_kernel<<<M, 256>>>(x, ln1_g, ln1_b, h);
    // 2. QKV = h @ W_attn + b_attn   [4096, 3072]
    sgemm_kernel<0><<<dim3(3072 / 128, M / 128), 256>>>(
        h, W_attn, b_attn, nullptr, qkv, M, 3072, 1024);
    // 3. attention -> y [4096, 1024]
    attn_kernel<<<dim3(32, 32), 256, ATTN_SMEM>>>(qkv, yb);
    // 4. x1 = x + y @ W_o + b_o
    sgemm_kernel<1><<<dim3(1024 / 128, M / 128), 256>>>(
        yb, W_o, b_o, x, x1, M, 1024, 1024);
    // 5. LN2
    ln_kernel<<<M, 256>>>(x1, ln2_g, ln2_b, h);
    // 6. fc = gelu(h @ W_fc + b_fc)  [4096, 4096]
    sgemm_kernel<2><<<dim3(4096 / 128, M / 128), 256>>>(
        h, W_fc, b_fc, nullptr, fc, M, 4096, 1024);
    // 7. out = x1 + fc @ W_fc2 + b_fc2
    sgemm_kernel<1><<<dim3(1024 / 128, M / 128), 256>>>(
        fc, W_fc2, b_fc2, x1, out, M, 1024, 4096);
}

// round 12
// speedup vs baseline: 2.0774x; 2.0719x over previous
#include <cuda_runtime.h>
#include <cuda_bf16.h>
#include <cstddef>
#include <cstdint>

typedef __nv_bfloat16 BF16;

// ---------------------------------------------------------------------------
// Scratch (device globals — no runtime allocation allowed)
// ---------------------------------------------------------------------------
__device__ float g_qkv[4096 * 3072];                    // QKV fp32
__device__ float g_x1 [4096 * 1024];                    // residual 1 fp32
__device__ BF16 g_h_hi [4096 * 1024], g_h_lo [4096 * 1024];   // LN out
__device__ BF16 g_y_hi [4096 * 1024], g_y_lo [4096 * 1024];   // attn out
__device__ BF16 g_fc_hi[4096 * 4096], g_fc_lo[4096 * 4096];   // FC out
__device__ BF16 g_wqkv_hi[1024 * 3072], g_wqkv_lo[1024 * 3072];
__device__ BF16 g_wo_hi  [1024 * 1024], g_wo_lo  [1024 * 1024];
__device__ BF16 g_wfc_hi [1024 * 4096], g_wfc_lo [1024 * 4096];
__device__ BF16 g_wfc2_hi[4096 * 1024], g_wfc2_lo[4096 * 1024];

// ---------------------------------------------------------------------------
// helpers
// ---------------------------------------------------------------------------
__device__ __forceinline__ float gelu_tanh(float v) {
    float u = 0.7978845608028654f * fmaf(0.044715f * v * v, v, v);
    float e = __expf(2.0f * u);
    return v * (1.0f - 1.0f / (e + 1.0f));
}

__device__ __forceinline__ void split1(float v, BF16& h, BF16& l) {
    h = __float2bfloat16(v);
    l = __float2bfloat16(v - __bfloat162float(h));
}

__device__ __forceinline__ void ldsm_x4(uint32_t& r0, uint32_t& r1,
                                        uint32_t& r2, uint32_t& r3,
                                        uint32_t addr) {
    asm volatile("ldmatrix.sync.aligned.m8n8.x4.shared.b16 {%0,%1,%2,%3}, [%4];\n"
                 : "=r"(r0), "=r"(r1), "=r"(r2), "=r"(r3) : "r"(addr));
}
__device__ __forceinline__ void ldsm_x4_t(uint32_t& r0, uint32_t& r1,
                                          uint32_t& r2, uint32_t& r3,
                                          uint32_t addr) {
    asm volatile("ldmatrix.sync.aligned.m8n8.x4.trans.shared.b16 {%0,%1,%2,%3}, [%4];\n"
                 : "=r"(r0), "=r"(r1), "=r"(r2), "=r"(r3) : "r"(addr));
}
__device__ __forceinline__ void mma_bf16(float* c, const uint32_t* a,
                                         uint32_t b0, uint32_t b1) {
    asm volatile(
        "mma.sync.aligned.m16n8k16.row.col.f32.bf16.bf16.f32 "
        "{%0,%1,%2,%3},{%4,%5,%6,%7},{%8,%9},{%0,%1,%2,%3};\n"
        : "+f"(c[0]), "+f"(c[1]), "+f"(c[2]), "+f"(c[3])
        : "r"(a[0]), "r"(a[1]), "r"(a[2]), "r"(a[3]), "r"(b0), "r"(b1));
}

// ---------------------------------------------------------------------------
// fp32 -> bf16 hi/lo split (weights)
// ---------------------------------------------------------------------------
__global__ void __launch_bounds__(256) split_kernel(
    const float* __restrict__ in, BF16* __restrict__ hi,
    BF16* __restrict__ lo, int n4)
{
    int i = blockIdx.x * blockDim.x + threadIdx.x;
    if (i >= n4) return;
    float4 v = reinterpret_cast<const float4*>(in)[i];
    BF16 hv[4], lv[4];
    split1(v.x, hv[0], lv[0]);
    split1(v.y, hv[1], lv[1]);
    split1(v.z, hv[2], lv[2]);
    split1(v.w, hv[3], lv[3]);
    reinterpret_cast<uint2*>(hi)[i] = *reinterpret_cast<uint2*>(hv);
    reinterpret_cast<uint2*>(lo)[i] = *reinterpret_cast<uint2*>(lv);
}

// ---------------------------------------------------------------------------
// LayerNorm: one block per row of 1024, writes bf16 hi/lo
// ---------------------------------------------------------------------------
__global__ void __launch_bounds__(256) ln_kernel(
    const float* __restrict__ x, const float* __restrict__ g,
    const float* __restrict__ b, BF16* __restrict__ o_hi,
    BF16* __restrict__ o_lo)
{
    const int row = blockIdx.x;
    const int tid = threadIdx.x;
    float4 v = reinterpret_cast<const float4*>(x + (size_t)row * 1024)[tid];
    float s  = v.x + v.y + v.z + v.w;
    float ss = v.x * v.x + v.y * v.y + v.z * v.z + v.w * v.w;
    #pragma unroll
    for (int off = 16; off; off >>= 1) {
        s  += __shfl_down_sync(0xffffffffu, s, off);
        ss += __shfl_down_sync(0xffffffffu, ss, off);
    }
    __shared__ float ws[8], wss[8];
    const int wid = tid >> 5, lane = tid & 31;
    if (lane == 0) { ws[wid] = s; wss[wid] = ss; }
    __syncthreads();
    s = 0.f; ss = 0.f;
    #pragma unroll
    for (int w = 0; w < 8; w++) { s += ws[w]; ss += wss[w]; }
    const float mean = s * (1.0f / 1024.0f);
    const float var  = ss * (1.0f / 1024.0f) - mean * mean;
    const float rstd = rsqrtf(var + 1e-5f);
    float4 gv = reinterpret_cast<const float4*>(g)[tid];
    float4 bv = reinterpret_cast<const float4*>(b)[tid];
    float r0 = (v.x - mean) * rstd * gv.x + bv.x;
    float r1 = (v.y - mean) * rstd * gv.y + bv.y;
    float r2 = (v.z - mean) * rstd * gv.z + bv.z;
    float r3 = (v.w - mean) * rstd * gv.w + bv.w;
    BF16 hv[4], lv[4];
    split1(r0, hv[0], lv[0]);
    split1(r1, hv[1], lv[1]);
    split1(r2, hv[2], lv[2]);
    split1(r3, hv[3], lv[3]);
    const size_t idx = (size_t)row * 1024 + tid * 4;
    *reinterpret_cast<uint2*>(o_hi + idx) = *reinterpret_cast<uint2*>(hv);
    *reinterpret_cast<uint2*>(o_lo + idx) = *reinterpret_cast<uint2*>(lv);
}

// ---------------------------------------------------------------------------
// bf16 split-precision GEMM on tensor cores
//   C[M,N] = (Ah+Al)[M,K] @ (Bh+Bl)[K,N] + bias (+Res / +GELU per EPI)
//   3-term: Ah*Bh + Ah*Bl + Al*Bh, fp32 accumulate
//   EPI 0: bias -> Cf (fp32)
//   EPI 1: bias + Res -> Cf (fp32)
//   EPI 2: bias + GELU -> Ch/Cl (bf16 hi/lo)
// Tile: 128x128x32, 256 threads (8 warps, 2x4), warp tile 64x32.
// SMEM (bf16 elems): A_hi[2][128][40], A_lo, B_hi[2][32][136], B_lo = 75776 B
// ---------------------------------------------------------------------------
#define SM_AHI 0
#define SM_ALO 10240
#define SM_BHI 20480
#define SM_BLO 29184
#define SM_ELEMS 37888
#define A_BUF 5120
#define B_BUF 4352

template <int EPI>
__global__ void __launch_bounds__(256, 1) hgemm_kernel(
    const BF16* __restrict__ Ah, const BF16* __restrict__ Al,
    const BF16* __restrict__ Bh, const BF16* __restrict__ Bl,
    const float* __restrict__ bias, const float* __restrict__ Res,
    float* __restrict__ Cf, BF16* __restrict__ Ch, BF16* __restrict__ Cl,
    int M, int N, int K)
{
    extern __shared__ BF16 smb[];
    const int tid  = threadIdx.x;
    const int lane = tid & 31, warp = tid >> 5;
    const int wm = (warp >> 2) * 64;     // 0 / 64
    const int wn = (warp & 3) * 32;      // 0..96
    const int block_row = blockIdx.y * 128;
    const int block_col = blockIdx.x * 128;

    // gmem loader coords (uint4 = 8 bf16)
    const int ar = tid >> 2;             // A rows ar, ar+64
    const int ac = (tid & 3) * 8;        // A k-col
    const int br = tid >> 4;             // B rows br, br+16
    const int bc = (tid & 15) * 8;       // B n-col

    const uint32_t smbase =
        (uint32_t)__cvta_generic_to_shared(smb);

    // ldmatrix lane constants
    const int a_row = lane & 15;
    const int a_kc  = (lane >> 4) * 8;
    const int b_kr  = lane & 15;
    const int b_nc  = wn + (lane >> 4) * 8;

    const int nTiles = K >> 5;

    // ---- prologue: tile 0 -> buffer 0 ----
    {
        uint4 a0 = *reinterpret_cast<const uint4*>(Ah + (size_t)(block_row + ar) * K + ac);
        uint4 a1 = *reinterpret_cast<const uint4*>(Ah + (size_t)(block_row + ar + 64) * K + ac);
        uint4 a2 = *reinterpret_cast<const uint4*>(Al + (size_t)(block_row + ar) * K + ac);
        uint4 a3 = *reinterpret_cast<const uint4*>(Al + (size_t)(block_row + ar + 64) * K + ac);
        uint4 b0 = *reinterpret_cast<const uint4*>(Bh + (size_t)br * N + block_col + bc);
        uint4 b1 = *reinterpret_cast<const uint4*>(Bh + (size_t)(br + 16) * N + block_col + bc);
        uint4 b2 = *reinterpret_cast<const uint4*>(Bl + (size_t)br * N + block_col + bc);
        uint4 b3 = *reinterpret_cast<const uint4*>(Bl + (size_t)(br + 16) * N + block_col + bc);
        *reinterpret_cast<uint4*>(smb + SM_AHI + ar * 40 + ac) = a0;
        *reinterpret_cast<uint4*>(smb + SM_AHI + (ar + 64) * 40 + ac) = a1;
        *reinterpret_cast<uint4*>(smb + SM_ALO + ar * 40 + ac) = a2;
        *reinterpret_cast<uint4*>(smb + SM_ALO + (ar + 64) * 40 + ac) = a3;
        *reinterpret_cast<uint4*>(smb + SM_BHI + br * 136 + bc) = b0;
        *reinterpret_cast<uint4*>(smb + SM_BHI + (br + 16) * 136 + bc) = b1;
        *reinterpret_cast<uint4*>(smb + SM_BLO + br * 136 + bc) = b2;
        *reinterpret_cast<uint4*>(smb + SM_BLO + (br + 16) * 136 + bc) = b3;
    }
    __syncthreads();

    float acc[4][4][4];
    #pragma unroll
    for (int i = 0; i < 4; i++)
        #pragma unroll
        for (int j = 0; j < 4; j++)
            #pragma unroll
            for (int e = 0; e < 4; e++) acc[i][j][e] = 0.f;

    for (int kt = 0; kt < nTiles; kt++) {
        const int buf = kt & 1, nxt = buf ^ 1;
        const bool has = (kt + 1 < nTiles);
        uint4 pa[4], pb[4];
        if (has) {
            const int k0 = (kt + 1) << 5;
            pa[0] = *reinterpret_cast<const uint4*>(Ah + (size_t)(block_row + ar) * K + k0 + ac);
            pa[1] = *reinterpret_cast<const uint4*>(Ah + (size_t)(block_row + ar + 64) * K + k0 + ac);
            pa[2] = *reinterpret_cast<const uint4*>(Al + (size_t)(block_row + ar) * K + k0 + ac);
            pa[3] = *reinterpret_cast<const uint4*>(Al + (size_t)(block_row + ar + 64) * K + k0 + ac);
            pb[0] = *reinterpret_cast<const uint4*>(Bh + (size_t)(k0 + br) * N + block_col + bc);
            pb[1] = *reinterpret_cast<const uint4*>(Bh + (size_t)(k0 + br + 16) * N + block_col + bc);
            pb[2] = *reinterpret_cast<const uint4*>(Bl + (size_t)(k0 + br) * N + block_col + bc);
            pb[3] = *reinterpret_cast<const uint4*>(Bl + (size_t)(k0 + br + 16) * N + block_col + bc);
        }

        const uint32_t aBaseH = smbase + 2u * (SM_AHI + buf * A_BUF);
        const uint32_t aBaseL = smbase + 2u * (SM_ALO + buf * A_BUF);
        const uint32_t bBaseH = smbase + 2u * (SM_BHI + buf * B_BUF);
        const uint32_t bBaseL = smbase + 2u * (SM_BLO + buf * B_BUF);

        #pragma unroll
        for (int k16 = 0; k16 < 2; k16++) {
            uint32_t bh[8], bl[8];
            #pragma unroll
            for (int ni2 = 0; ni2 < 2; ni2++) {
                const uint32_t boff =
                    2u * ((k16 * 16 + b_kr) * 136 + b_nc + ni2 * 16);
                ldsm_x4_t(bh[ni2 * 4 + 0], bh[ni2 * 4 + 1],
                          bh[ni2 * 4 + 2], bh[ni2 * 4 + 3], bBaseH + boff);
                ldsm_x4_t(bl[ni2 * 4 + 0], bl[ni2 * 4 + 1],
                          bl[ni2 * 4 + 2], bl[ni2 * 4 + 3], bBaseL + boff);
            }
            #pragma unroll
            for (int mi = 0; mi < 4; mi++) {
                uint32_t ah[4], al[4];
                const uint32_t aoff =
                    2u * ((wm + mi * 16 + a_row) * 40 + k16 * 16 + a_kc);
                ldsm_x4(ah[0], ah[1], ah[2], ah[3], aBaseH + aoff);
                ldsm_x4(al[0], al[1], al[2], al[3], aBaseL + aoff);
                #pragma unroll
                for (int ni = 0; ni < 4; ni++) {
                    mma_bf16(acc[mi][ni], ah, bh[ni * 2], bh[ni * 2 + 1]);
                    mma_bf16(acc[mi][ni], ah, bl[ni * 2], bl[ni * 2 + 1]);
                    mma_bf16(acc[mi][ni], al, bh[ni * 2], bh[ni * 2 + 1]);
                }
            }
        }

        if (has) {
            *reinterpret_cast<uint4*>(smb + SM_AHI + nxt * A_BUF + ar * 40 + ac) = pa[0];
            *reinterpret_cast<uint4*>(smb + SM_AHI + nxt * A_BUF + (ar + 64) * 40 + ac) = pa[1];
            *reinterpret_cast<uint4*>(smb + SM_ALO + nxt * A_BUF + ar * 40 + ac) = pa[2];
            *reinterpret_cast<uint4*>(smb + SM_ALO + nxt * A_BUF + (ar + 64) * 40 + ac) = pa[3];
            *reinterpret_cast<uint4*>(smb + SM_BHI + nxt * B_BUF + br * 136 + bc) = pb[0];
            *reinterpret_cast<uint4*>(smb + SM_BHI + nxt * B_BUF + (br + 16) * 136 + bc) = pb[1];
            *reinterpret_cast<uint4*>(smb + SM_BLO + nxt * B_BUF + br * 136 + bc) = pb[2];
            *reinterpret_cast<uint4*>(smb + SM_BLO + nxt * B_BUF + (br + 16) * 136 + bc) = pb[3];
        }
        __syncthreads();
    }

    // ---- epilogue ----
    const int gg = lane >> 2, t2 = (lane & 3) * 2;
    #pragma unroll
    for (int mi = 0; mi < 4; mi++) {
        const int row = block_row + wm + mi * 16 + gg;
        #pragma unroll
        for (int ni = 0; ni < 4; ni++) {
            const int col = block_col + wn + ni * 8 + t2;
            const float2 bb = *reinterpret_cast<const float2*>(bias + col);
            float v00 = acc[mi][ni][0] + bb.x;
            float v01 = acc[mi][ni][1] + bb.y;
            float v10 = acc[mi][ni][2] + bb.x;
            float v11 = acc[mi][ni][3] + bb.y;
            if (EPI == 1) {
                float2 r0 = *reinterpret_cast<const float2*>(Res + (size_t)row * N + col);
                float2 r1 = *reinterpret_cast<const float2*>(Res + (size_t)(row + 8) * N + col);
                v00 += r0.x; v01 += r0.y; v10 += r1.x; v11 += r1.y;
            }
            if (EPI <= 1) {
                float2 o0 = make_float2(v00, v01);
                float2 o1 = make_float2(v10, v11);
                *reinterpret_cast<float2*>(Cf + (size_t)row * N + col) = o0;
                *reinterpret_cast<float2*>(Cf + (size_t)(row + 8) * N + col) = o1;
            } else {
                v00 = gelu_tanh(v00); v01 = gelu_tanh(v01);
                v10 = gelu_tanh(v10); v11 = gelu_tanh(v11);
                BF16 h0[2], l0[2], h1[2], l1[2];
                split1(v00, h0[0], l0[0]); split1(v01, h0[1], l0[1]);
                split1(v10, h1[0], l1[0]); split1(v11, h1[1], l1[1]);
                *reinterpret_cast<uint32_t*>(Ch + (size_t)row * N + col) =
                    *reinterpret_cast<uint32_t*>(h0);
                *reinterpret_cast<uint32_t*>(Cl + (size_t)row * N + col) =
                    *reinterpret_cast<uint32_t*>(l0);
                *reinterpret_cast<uint32_t*>(Ch + (size_t)(row + 8) * N + col) =
                    *reinterpret_cast<uint32_t*>(h1);
                *reinterpret_cast<uint32_t*>(Cl + (size_t)(row + 8) * N + col) =
                    *reinterpret_cast<uint32_t*>(l1);
            }
        }
    }
}

// ---------------------------------------------------------------------------
// Flash attention (fp32, causal): 64x64 tiles, online softmax.
// Writes bf16 hi/lo output for the W_o GEMM. Dynamic SMEM = 67584 bytes.
// ---------------------------------------------------------------------------
__global__ void __launch_bounds__(256) attn_kernel(
    const float* __restrict__ qkv, BF16* __restrict__ y_hi,
    BF16* __restrict__ y_lo)
{
    const int T = 2048, C3 = 3072;
    extern __shared__ float sm[];
    float* Qs   = sm;
    float* KsT  = Qs  + 64 * 64;
    float* Vs   = KsT + 64 * 68;
    float* Ss   = Vs  + 64 * 64;
    float* m_s  = Ss  + 64 * 65;
    float* l_s  = m_s + 64;
    float* al_s = l_s + 64;

    const int q0 = blockIdx.x * 64;
    const int bh = blockIdx.y;
    const int bb = bh >> 4, hh = bh & 15;
    const float* qbase = qkv + (size_t)bb * T * C3 + hh * 64;
    const float* kbase = qbase + 1024;
    const float* vbase = qbase + 2048;

    const int tid = threadIdx.x;
    const int tx = tid & 15, ty = tid >> 4;
    const int r0 = ty * 4, c0 = tx * 4;

    #pragma unroll
    for (int i = 0; i < 4; i++) {
        const int v = tid + i * 256;
        const int r = v >> 4, d4 = (v & 15) * 4;
        float4 q = *reinterpret_cast<const float4*>(qbase + (size_t)(q0 + r) * C3 + d4);
        q.x *= 0.125f; q.y *= 0.125f; q.z *= 0.125f; q.w *= 0.125f;
        *reinterpret_cast<float4*>(Qs + r * 64 + d4) = q;
    }
    if (tid < 64) { m_s[tid] = -1e30f; l_s[tid] = 0.f; }

    float o[4][4];
    #pragma unroll
    for (int i = 0; i < 4; i++)
        #pragma unroll
        for (int j = 0; j < 4; j++) o[i][j] = 0.f;

    const int ntiles = (q0 >> 6) + 1;
    for (int jt = 0; jt < ntiles; jt++) {
        const int j0 = jt * 64;
        __syncthreads();
        #pragma unroll
        for (int i = 0; i < 4; i++) {
            const int v = tid + i * 256;
            const int jr = v & 63, d4 = (v >> 6) * 4;
            float4 kk = *reinterpret_cast<const float4*>(kbase + (size_t)(j0 + jr) * C3 + d4);
            KsT[(d4 + 0) * 68 + jr] = kk.x;
            KsT[(d4 + 1) * 68 + jr] = kk.y;
            KsT[(d4 + 2) * 68 + jr] = kk.z;
            KsT[(d4 + 3) * 68 + jr] = kk.w;
        }
        #pragma unroll
        for (int i = 0; i < 4; i++) {
            const int v = tid + i * 256;
            const int jr = v >> 4, d4 = (v & 15) * 4;
            float4 vv = *reinterpret_cast<const float4*>(vbase + (size_t)(j0 + jr) * C3 + d4);
            *reinterpret_cast<float4*>(Vs + jr * 64 + d4) = vv;
        }
        __syncthreads();

        float s4[4][4];
        #pragma unroll
        for (int i = 0; i < 4; i++)
            #pragma unroll
            for (int j = 0; j < 4; j++) s4[i][j] = 0.f;
        #pragma unroll 8
        for (int d = 0; d < 64; d++) {
            const float4 kv = *reinterpret_cast<const float4*>(KsT + d * 68 + c0);
            const float q0v = Qs[(r0 + 0) * 64 + d];
            const float q1v = Qs[(r0 + 1) * 64 + d];
            const float q2v = Qs[(r0 + 2) * 64 + d];
            const float q3v = Qs[(r0 + 3) * 64 + d];
            s4[0][0] = fmaf(q0v, kv.x, s4[0][0]); s4[0][1] = fmaf(q0v, kv.y, s4[0][1]);
            s4[0][2] = fmaf(q0v, kv.z, s4[0][2]); s4[0][3] = fmaf(q0v, kv.w, s4[0][3]);
            s4[1][0] = fmaf(q1v, kv.x, s4[1][0]); s4[1][1] = fmaf(q1v, kv.y, s4[1][1]);
            s4[1][2] = fmaf(q1v, kv.z, s4[1][2]); s4[1][3] = fmaf(q1v, kv.w, s4[1][3]);
            s4[2][0] = fmaf(q2v, kv.x, s4[2][0]); s4[2][1] = fmaf(q2v, kv.y, s4[2][1]);
            s4[2][2] = fmaf(q2v, kv.z, s4[2][2]); s4[2][3] = fmaf(q2v, kv.w, s4[2][3]);
            s4[3][0] = fmaf(q3v, kv.x, s4[3][0]); s4[3][1] = fmaf(q3v, kv.y, s4[3][1]);
            s4[3][2] = fmaf(q3v, kv.z, s4[3][2]); s4[3][3] = fmaf(q3v, kv.w, s4[3][3]);
        }
        if (j0 == q0) {
            #pragma unroll
            for (int rr = 0; rr < 4; rr++)
                #pragma unroll
                for (int cc = 0; cc < 4; cc++)
                    if (c0 + cc > r0 + rr) s4[rr][cc] = -1e30f;
        }
        #pragma unroll
        for (int rr = 0; rr < 4; rr++)
            #pragma unroll
            for (int cc = 0; cc < 4; cc++)
                Ss[(r0 + rr) * 65 + c0 + cc] = s4[rr][cc];
        __syncthreads();

        {
            const int row = tid >> 2, part = tid & 3;
            float* srow = Ss + row * 65 + part * 16;
            float mx = -1e30f;
            #pragma unroll
            for (int j = 0; j < 16; j++) mx = fmaxf(mx, srow[j]);
            mx = fmaxf(mx, __shfl_xor_sync(0xffffffffu, mx, 1));
            mx = fmaxf(mx, __shfl_xor_sync(0xffffffffu, mx, 2));
            const float m_old = m_s[row];
            const float m_new = fmaxf(m_old, mx);
            float sum = 0.f;
            #pragma unroll
            for (int j = 0; j < 16; j++) {
                const float p = __expf(srow[j] - m_new);
                srow[j] = p;
                sum += p;
            }
            sum += __shfl_xor_sync(0xffffffffu, sum, 1);
            sum += __shfl_xor_sync(0xffffffffu, sum, 2);
            if (part == 0) {
                const float alpha = __expf(m_old - m_new);
                al_s[row] = alpha;
                m_s[row]  = m_new;
                l_s[row]  = l_s[row] * alpha + sum;
            }
        }
        __syncthreads();

        const float a0 = al_s[r0 + 0], a1 = al_s[r0 + 1];
        const float a2 = al_s[r0 + 2], a3 = al_s[r0 + 3];
        #pragma unroll
        for (int cc = 0; cc < 4; cc++) {
            o[0][cc] *= a0; o[1][cc] *= a1; o[2][cc] *= a2; o[3][cc] *= a3;
        }
        #pragma unroll 8
        for (int j = 0; j < 64; j++) {
            const float4 vv = *reinterpret_cast<const float4*>(Vs + j * 64 + c0);
            const float p0 = Ss[(r0 + 0) * 65 + j];
            const float p1 = Ss[(r0 + 1) * 65 + j];
            const float p2 = Ss[(r0 + 2) * 65 + j];
            const float p3 = Ss[(r0 + 3) * 65 + j];
            o[0][0] = fmaf(p0, vv.x, o[0][0]); o[0][1] = fmaf(p0, vv.y, o[0][1]);
            o[0][2] = fmaf(p0, vv.z, o[0][2]); o[0][3] = fmaf(p0, vv.w, o[0][3]);
            o[1][0] = fmaf(p1, vv.x, o[1][0]); o[1][1] = fmaf(p1, vv.y, o[1][1]);
            o[1][2] = fmaf(p1, vv.z, o[1][2]); o[1][3] = fmaf(p1, vv.w, o[1][3]);
            o[2][0] = fmaf(p2, vv.x, o[2][0]); o[2][1] = fmaf(p2, vv.y, o[2][1]);
            o[2][2] = fmaf(p2, vv.z, o[2][2]); o[2][3] = fmaf(p2, vv.w, o[2][3]);
            o[3][0] = fmaf(p3, vv.x, o[3][0]); o[3][1] = fmaf(p3, vv.y, o[3][1]);
            o[3][2] = fmaf(p3, vv.z, o[3][2]); o[3][3] = fmaf(p3, vv.w, o[3][3]);
        }
    }

    #pragma unroll
    for (int rr = 0; rr < 4; rr++) {
        const float inv = 1.0f / l_s[r0 + rr];
        BF16 hv[4], lv[4];
        split1(o[rr][0] * inv, hv[0], lv[0]);
        split1(o[rr][1] * inv, hv[1], lv[1]);
        split1(o[rr][2] * inv, hv[2], lv[2]);
        split1(o[rr][3] * inv, hv[3], lv[3]);
        const size_t idx = ((size_t)bb * T + q0 + r0 + rr) * 1024 + hh * 64 + c0;
        *reinterpret_cast<uint2*>(y_hi + idx) = *reinterpret_cast<uint2*>(hv);
        *reinterpret_cast<uint2*>(y_lo + idx) = *reinterpret_cast<uint2*>(lv);
    }
}

// ---------------------------------------------------------------------------
// Launch
// ---------------------------------------------------------------------------
extern "C" void kernel_launch(void* const* d_in, const int* in_sizes, int n_in,
                              void* d_out, int out_size)
{
    const float* x      = (const float*)d_in[0];
    const float* ln1_g  = (const float*)d_in[1];
    const float* ln1_b  = (const float*)d_in[2];
    const float* W_attn = (const float*)d_in[3];
    const float* b_attn = (const float*)d_in[4];
    const float* W_o    = (const float*)d_in[5];
    const float* b_o    = (const float*)d_in[6];
    const float* ln2_g  = (const float*)d_in[7];
    const float* ln2_b  = (const float*)d_in[8];
    const float* W_fc   = (const float*)d_in[9];
    const float* b_fc   = (const float*)d_in[10];
    const float* W_fc2  = (const float*)d_in[11];
    const float* b_fc2  = (const float*)d_in[12];
    float* out = (float*)d_out;

    float *qkv, *x1;
    BF16 *h_hi, *h_lo, *y_hi, *y_lo, *fc_hi, *fc_lo;
    BF16 *wq_hi, *wq_lo, *wo_hi, *wo_lo, *wf_hi, *wf_lo, *w2_hi, *w2_lo;
    cudaGetSymbolAddress((void**)&qkv,   g_qkv);
    cudaGetSymbolAddress((void**)&x1,    g_x1);
    cudaGetSymbolAddress((void**)&h_hi,  g_h_hi);
    cudaGetSymbolAddress((void**)&h_lo,  g_h_lo);
    cudaGetSymbolAddress((void**)&y_hi,  g_y_hi);
    cudaGetSymbolAddress((void**)&y_lo,  g_y_lo);
    cudaGetSymbolAddress((void**)&fc_hi, g_fc_hi);
    cudaGetSymbolAddress((void**)&fc_lo, g_fc_lo);
    cudaGetSymbolAddress((void**)&wq_hi, g_wqkv_hi);
    cudaGetSymbolAddress((void**)&wq_lo, g_wqkv_lo);
    cudaGetSymbolAddress((void**)&wo_hi, g_wo_hi);
    cudaGetSymbolAddress((void**)&wo_lo, g_wo_lo);
    cudaGetSymbolAddress((void**)&wf_hi, g_wfc_hi);
    cudaGetSymbolAddress((void**)&wf_lo, g_wfc_lo);
    cudaGetSymbolAddress((void**)&w2_hi, g_wfc2_hi);
    cudaGetSymbolAddress((void**)&w2_lo, g_wfc2_lo);

    const int GEMM_SMEM = SM_ELEMS * 2;   // 75776 bytes
    const int ATTN_SMEM = 67584;
    cudaFuncSetAttribute(hgemm_kernel<0>,
                         cudaFuncAttributeMaxDynamicSharedMemorySize, GEMM_SMEM);
    cudaFuncSetAttribute(hgemm_kernel<1>,
                         cudaFuncAttributeMaxDynamicSharedMemorySize, GEMM_SMEM);
    cudaFuncSetAttribute(hgemm_kernel<2>,
                         cudaFuncAttributeMaxDynamicSharedMemorySize, GEMM_SMEM);
    cudaFuncSetAttribute(attn_kernel,
                         cudaFuncAttributeMaxDynamicSharedMemorySize, ATTN_SMEM);

    const int M = 4096;

    // 0. split weights to bf16 hi/lo
    split_kernel<<<(1024 * 3072 / 4 + 255) / 256, 256>>>(W_attn, wq_hi, wq_lo, 1024 * 3072 / 4);
    split_kernel<<<(1024 * 1024 / 4 + 255) / 256, 256>>>(W_o,    wo_hi, wo_lo, 1024 * 1024 / 4);
    split_kernel<<<(1024 * 4096 / 4 + 255) / 256, 256>>>(W_fc,   wf_hi, wf_lo, 1024 * 4096 / 4);
    split_kernel<<<(4096 * 1024 / 4 + 255) / 256, 256>>>(W_fc2,  w2_hi, w2_lo, 4096 * 1024 / 4);

    // 1. LN1 -> h (bf16 hi/lo)
    ln_kernel<<<M, 256>>>(x, ln1_g, ln1_b, h_hi, h_lo);
    // 2. QKV = h @ W_attn + b_attn  (fp32 out)
    hgemm_kernel<0><<<dim3(3072 / 128, M / 128), 256, GEMM_SMEM>>>(
        h_hi, h_lo, wq_hi, wq_lo, b_attn, nullptr, qkv, nullptr, nullptr,
        M, 3072, 1024);
    // 3. attention -> y (bf16 hi/lo)
    attn_kernel<<<dim3(32, 32), 256, ATTN_SMEM>>>(qkv, y_hi, y_lo);
    // 4. x1 = x + y @ W_o + b_o
    hgemm_kernel<1><<<dim3(1024 / 128, M / 128), 256, GEMM_SMEM>>>(
        y_hi, y_lo, wo_hi, wo_lo, b_o, x, x1, nullptr, nullptr,
        M, 1024, 1024);
    // 5. LN2 -> h (bf16 hi/lo)
    ln_kernel<<<M, 256>>>(x1, ln2_g, ln2_b, h_hi, h_lo);
    // 6. fc = gelu(h @ W_fc + b_fc)  (bf16 hi/lo out)
    hgemm_kernel<2><<<dim3(4096 / 128, M / 128), 256, GEMM_SMEM>>>(
        h_hi, h_lo, wf_hi, wf_lo, b_fc, nullptr, nullptr, fc_hi, fc_lo,
        M, 4096, 1024);
    // 7. out = x1 + fc @ W_fc2 + b_fc2
    hgemm_kernel<1><<<dim3(1024 / 128, M / 128), 256, GEMM_SMEM>>>(
        fc_hi, fc_lo, w2_hi, w2_lo, b_fc2, x1, out, nullptr, nullptr,
        M, 1024, 4096);
}

// round 14
// speedup vs baseline: 2.0776x; 1.0001x over previous
#include <cuda_runtime.h>
#include <cuda_bf16.h>
#include <cstddef>
#include <cstdint>

typedef __nv_bfloat16 BF16;

// ---------------------------------------------------------------------------
// Scratch (device globals — no runtime allocation allowed)
// ---------------------------------------------------------------------------
__device__ float g_qkv[4096 * 3072];                    // QKV fp32
__device__ float g_x1 [4096 * 1024];                    // residual 1 fp32
__device__ BF16 g_h_hi [4096 * 1024], g_h_lo [4096 * 1024];   // LN out
__device__ BF16 g_y_hi [4096 * 1024], g_y_lo [4096 * 1024];   // attn out
__device__ BF16 g_fc_hi[4096 * 4096], g_fc_lo[4096 * 4096];   // FC out
__device__ BF16 g_wqkv_hi[1024 * 3072], g_wqkv_lo[1024 * 3072];
__device__ BF16 g_wo_hi  [1024 * 1024], g_wo_lo  [1024 * 1024];
__device__ BF16 g_wfc_hi [1024 * 4096], g_wfc_lo [1024 * 4096];
__device__ BF16 g_wfc2_hi[4096 * 1024], g_wfc2_lo[4096 * 1024];

// ---------------------------------------------------------------------------
// helpers
// ---------------------------------------------------------------------------
__device__ __forceinline__ float gelu_tanh(float v) {
    float u = 0.7978845608028654f * fmaf(0.044715f * v * v, v, v);
    float e = __expf(2.0f * u);
    return v * (1.0f - 1.0f / (e + 1.0f));
}

__device__ __forceinline__ void split1(float v, BF16& h, BF16& l) {
    h = __float2bfloat16(v);
    l = __float2bfloat16(v - __bfloat162float(h));
}

__device__ __forceinline__ void ldsm_x4(uint32_t& r0, uint32_t& r1,
                                        uint32_t& r2, uint32_t& r3,
                                        uint32_t addr) {
    asm volatile("ldmatrix.sync.aligned.m8n8.x4.shared.b16 {%0,%1,%2,%3}, [%4];\n"
                 : "=r"(r0), "=r"(r1), "=r"(r2), "=r"(r3) : "r"(addr));
}
__device__ __forceinline__ void ldsm_x4_t(uint32_t& r0, uint32_t& r1,
                                          uint32_t& r2, uint32_t& r3,
                                          uint32_t addr) {
    asm volatile("ldmatrix.sync.aligned.m8n8.x4.trans.shared.b16 {%0,%1,%2,%3}, [%4];\n"
                 : "=r"(r0), "=r"(r1), "=r"(r2), "=r"(r3) : "r"(addr));
}
__device__ __forceinline__ void mma_bf16(float* c, const uint32_t* a,
                                         uint32_t b0, uint32_t b1) {
    asm volatile(
        "mma.sync.aligned.m16n8k16.row.col.f32.bf16.bf16.f32 "
        "{%0,%1,%2,%3},{%4,%5,%6,%7},{%8,%9},{%0,%1,%2,%3};\n"
        : "+f"(c[0]), "+f"(c[1]), "+f"(c[2]), "+f"(c[3])
        : "r"(a[0]), "r"(a[1]), "r"(a[2]), "r"(a[3]), "r"(b0), "r"(b1));
}

// ---------------------------------------------------------------------------
// fp32 -> bf16 hi/lo split (weights)
// ---------------------------------------------------------------------------
__global__ void __launch_bounds__(256) split_kernel(
    const float* __restrict__ in, BF16* __restrict__ hi,
    BF16* __restrict__ lo, int n4)
{
    int i = blockIdx.x * blockDim.x + threadIdx.x;
    if (i >= n4) return;
    float4 v = reinterpret_cast<const float4*>(in)[i];
    BF16 hv[4], lv[4];
    split1(v.x, hv[0], lv[0]);
    split1(v.y, hv[1], lv[1]);
    split1(v.z, hv[2], lv[2]);
    split1(v.w, hv[3], lv[3]);
    reinterpret_cast<uint2*>(hi)[i] = *reinterpret_cast<uint2*>(hv);
    reinterpret_cast<uint2*>(lo)[i] = *reinterpret_cast<uint2*>(lv);
}

// ---------------------------------------------------------------------------
// LayerNorm: one block per row of 1024, writes bf16 hi/lo
// ---------------------------------------------------------------------------
__global__ void __launch_bounds__(256) ln_kernel(
    const float* __restrict__ x, const float* __restrict__ g,
    const float* __restrict__ b, BF16* __restrict__ o_hi,
    BF16* __restrict__ o_lo)
{
    const int row = blockIdx.x;
    const int tid = threadIdx.x;
    float4 v = reinterpret_cast<const float4*>(x + (size_t)row * 1024)[tid];
    float s  = v.x + v.y + v.z + v.w;
    float ss = v.x * v.x + v.y * v.y + v.z * v.z + v.w * v.w;
    #pragma unroll
    for (int off = 16; off; off >>= 1) {
        s  += __shfl_down_sync(0xffffffffu, s, off);
        ss += __shfl_down_sync(0xffffffffu, ss, off);
    }
    __shared__ float ws[8], wss[8];
    const int wid = tid >> 5, lane = tid & 31;
    if (lane == 0) { ws[wid] = s; wss[wid] = ss; }
    __syncthreads();
    s = 0.f; ss = 0.f;
    #pragma unroll
    for (int w = 0; w < 8; w++) { s += ws[w]; ss += wss[w]; }
    const float mean = s * (1.0f / 1024.0f);
    const float var  = ss * (1.0f / 1024.0f) - mean * mean;
    const float rstd = rsqrtf(var + 1e-5f);
    float4 gv = reinterpret_cast<const float4*>(g)[tid];
    float4 bv = reinterpret_cast<const float4*>(b)[tid];
    float r0 = (v.x - mean) * rstd * gv.x + bv.x;
    float r1 = (v.y - mean) * rstd * gv.y + bv.y;
    float r2 = (v.z - mean) * rstd * gv.z + bv.z;
    float r3 = (v.w - mean) * rstd * gv.w + bv.w;
    BF16 hv[4], lv[4];
    split1(r0, hv[0], lv[0]);
    split1(r1, hv[1], lv[1]);
    split1(r2, hv[2], lv[2]);
    split1(r3, hv[3], lv[3]);
    const size_t idx = (size_t)row * 1024 + tid * 4;
    *reinterpret_cast<uint2*>(o_hi + idx) = *reinterpret_cast<uint2*>(hv);
    *reinterpret_cast<uint2*>(o_lo + idx) = *reinterpret_cast<uint2*>(lv);
}

// ---------------------------------------------------------------------------
// bf16 split-precision GEMM on tensor cores
//   C[M,N] = (Ah+Al)[M,K] @ (Bh+Bl)[K,N] + bias (+Res / +GELU per EPI)
//   3-term: Ah*Bh + Ah*Bl + Al*Bh, fp32 accumulate
//   EPI 0: bias -> Cf (fp32)
//   EPI 1: bias + Res -> Cf (fp32)
//   EPI 2: bias + GELU -> Ch/Cl (bf16 hi/lo)
// Tile: 128x128x32, 256 threads (8 warps, 2x4), warp tile 64x32.
// SMEM (bf16 elems): A_hi[2][128][40], A_lo, B_hi[2][32][136], B_lo = 75776 B
// ---------------------------------------------------------------------------
#define SM_AHI 0
#define SM_ALO 10240
#define SM_BHI 20480
#define SM_BLO 29184
#define SM_ELEMS 37888
#define A_BUF 5120
#define B_BUF 4352

template <int EPI>
__global__ void __launch_bounds__(256, 1) hgemm_kernel(
    const BF16* __restrict__ Ah, const BF16* __restrict__ Al,
    const BF16* __restrict__ Bh, const BF16* __restrict__ Bl,
    const float* __restrict__ bias, const float* __restrict__ Res,
    float* __restrict__ Cf, BF16* __restrict__ Ch, BF16* __restrict__ Cl,
    int M, int N, int K)
{
    extern __shared__ BF16 smb[];
    const int tid  = threadIdx.x;
    const int lane = tid & 31, warp = tid >> 5;
    const int wm = (warp >> 2) * 64;     // 0 / 64
    const int wn = (warp & 3) * 32;      // 0..96
    const int block_row = blockIdx.y * 128;
    const int block_col = blockIdx.x * 128;

    // gmem loader coords (uint4 = 8 bf16)
    const int ar = tid >> 2;             // A rows ar, ar+64
    const int ac = (tid & 3) * 8;        // A k-col
    const int br = tid >> 4;             // B rows br, br+16
    const int bc = (tid & 15) * 8;       // B n-col

    const uint32_t smbase =
        (uint32_t)__cvta_generic_to_shared(smb);

    // ldmatrix lane constants
    const int a_row = lane & 15;
    const int a_kc  = (lane >> 4) * 8;
    const int b_kr  = lane & 15;
    const int b_nc  = wn + (lane >> 4) * 8;

    const int nTiles = K >> 5;

    // ---- prologue: tile 0 -> buffer 0 ----
    {
        uint4 a0 = *reinterpret_cast<const uint4*>(Ah + (size_t)(block_row + ar) * K + ac);
        uint4 a1 = *reinterpret_cast<const uint4*>(Ah + (size_t)(block_row + ar + 64) * K + ac);
        uint4 a2 = *reinterpret_cast<const uint4*>(Al + (size_t)(block_row + ar) * K + ac);
        uint4 a3 = *reinterpret_cast<const uint4*>(Al + (size_t)(block_row + ar + 64) * K + ac);
        uint4 b0 = *reinterpret_cast<const uint4*>(Bh + (size_t)br * N + block_col + bc);
        uint4 b1 = *reinterpret_cast<const uint4*>(Bh + (size_t)(br + 16) * N + block_col + bc);
        uint4 b2 = *reinterpret_cast<const uint4*>(Bl + (size_t)br * N + block_col + bc);
        uint4 b3 = *reinterpret_cast<const uint4*>(Bl + (size_t)(br + 16) * N + block_col + bc);
        *reinterpret_cast<uint4*>(smb + SM_AHI + ar * 40 + ac) = a0;
        *reinterpret_cast<uint4*>(smb + SM_AHI + (ar + 64) * 40 + ac) = a1;
        *reinterpret_cast<uint4*>(smb + SM_ALO + ar * 40 + ac) = a2;
        *reinterpret_cast<uint4*>(smb + SM_ALO + (ar + 64) * 40 + ac) = a3;
        *reinterpret_cast<uint4*>(smb + SM_BHI + br * 136 + bc) = b0;
        *reinterpret_cast<uint4*>(smb + SM_BHI + (br + 16) * 136 + bc) = b1;
        *reinterpret_cast<uint4*>(smb + SM_BLO + br * 136 + bc) = b2;
        *reinterpret_cast<uint4*>(smb + SM_BLO + (br + 16) * 136 + bc) = b3;
    }
    __syncthreads();

    float acc[4][4][4];
    #pragma unroll
    for (int i = 0; i < 4; i++)
        #pragma unroll
        for (int j = 0; j < 4; j++)
            #pragma unroll
            for (int e = 0; e < 4; e++) acc[i][j][e] = 0.f;

    for (int kt = 0; kt < nTiles; kt++) {
        const int buf = kt & 1, nxt = buf ^ 1;
        const bool has = (kt + 1 < nTiles);
        uint4 pa[4], pb[4];
        if (has) {
            const int k0 = (kt + 1) << 5;
            pa[0] = *reinterpret_cast<const uint4*>(Ah + (size_t)(block_row + ar) * K + k0 + ac);
            pa[1] = *reinterpret_cast<const uint4*>(Ah + (size_t)(block_row + ar + 64) * K + k0 + ac);
            pa[2] = *reinterpret_cast<const uint4*>(Al + (size_t)(block_row + ar) * K + k0 + ac);
            pa[3] = *reinterpret_cast<const uint4*>(Al + (size_t)(block_row + ar + 64) * K + k0 + ac);
            pb[0] = *reinterpret_cast<const uint4*>(Bh + (size_t)(k0 + br) * N + block_col + bc);
            pb[1] = *reinterpret_cast<const uint4*>(Bh + (size_t)(k0 + br + 16) * N + block_col + bc);
            pb[2] = *reinterpret_cast<const uint4*>(Bl + (size_t)(k0 + br) * N + block_col + bc);
            pb[3] = *reinterpret_cast<const uint4*>(Bl + (size_t)(k0 + br + 16) * N + block_col + bc);
        }

        const uint32_t aBaseH = smbase + 2u * (SM_AHI + buf * A_BUF);
        const uint32_t aBaseL = smbase + 2u * (SM_ALO + buf * A_BUF);
        const uint32_t bBaseH = smbase + 2u * (SM_BHI + buf * B_BUF);
        const uint32_t bBaseL = smbase + 2u * (SM_BLO + buf * B_BUF);

        #pragma unroll
        for (int k16 = 0; k16 < 2; k16++) {
            uint32_t bh[8], bl[8];
            #pragma unroll
            for (int ni2 = 0; ni2 < 2; ni2++) {
                const uint32_t boff =
                    2u * ((k16 * 16 + b_kr) * 136 + b_nc + ni2 * 16);
                ldsm_x4_t(bh[ni2 * 4 + 0], bh[ni2 * 4 + 1],
                          bh[ni2 * 4 + 2], bh[ni2 * 4 + 3], bBaseH + boff);
                ldsm_x4_t(bl[ni2 * 4 + 0], bl[ni2 * 4 + 1],
                          bl[ni2 * 4 + 2], bl[ni2 * 4 + 3], bBaseL + boff);
            }
            #pragma unroll
            for (int mi = 0; mi < 4; mi++) {
                uint32_t ah[4], al[4];
                const uint32_t aoff =
                    2u * ((wm + mi * 16 + a_row) * 40 + k16 * 16 + a_kc);
                ldsm_x4(ah[0], ah[1], ah[2], ah[3], aBaseH + aoff);
                ldsm_x4(al[0], al[1], al[2], al[3], aBaseL + aoff);
                #pragma unroll
                for (int ni = 0; ni < 4; ni++) {
                    mma_bf16(acc[mi][ni], ah, bh[ni * 2], bh[ni * 2 + 1]);
                    mma_bf16(acc[mi][ni], ah, bl[ni * 2], bl[ni * 2 + 1]);
                    mma_bf16(acc[mi][ni], al, bh[ni * 2], bh[ni * 2 + 1]);
                }
            }
        }

        if (has) {
            *reinterpret_cast<uint4*>(smb + SM_AHI + nxt * A_BUF + ar * 40 + ac) = pa[0];
            *reinterpret_cast<uint4*>(smb + SM_AHI + nxt * A_BUF + (ar + 64) * 40 + ac) = pa[1];
            *reinterpret_cast<uint4*>(smb + SM_ALO + nxt * A_BUF + ar * 40 + ac) = pa[2];
            *reinterpret_cast<uint4*>(smb + SM_ALO + nxt * A_BUF + (ar + 64) * 40 + ac) = pa[3];
            *reinterpret_cast<uint4*>(smb + SM_BHI + nxt * B_BUF + br * 136 + bc) = pb[0];
            *reinterpret_cast<uint4*>(smb + SM_BHI + nxt * B_BUF + (br + 16) * 136 + bc) = pb[1];
            *reinterpret_cast<uint4*>(smb + SM_BLO + nxt * B_BUF + br * 136 + bc) = pb[2];
            *reinterpret_cast<uint4*>(smb + SM_BLO + nxt * B_BUF + (br + 16) * 136 + bc) = pb[3];
        }
        __syncthreads();
    }

    // ---- epilogue ----
    const int gg = lane >> 2, t2 = (lane & 3) * 2;
    #pragma unroll
    for (int mi = 0; mi < 4; mi++) {
        const int row = block_row + wm + mi * 16 + gg;
        #pragma unroll
        for (int ni = 0; ni < 4; ni++) {
            const int col = block_col + wn + ni * 8 + t2;
            const float2 bb = *reinterpret_cast<const float2*>(bias + col);
            float v00 = acc[mi][ni][0] + bb.x;
            float v01 = acc[mi][ni][1] + bb.y;
            float v10 = acc[mi][ni][2] + bb.x;
            float v11 = acc[mi][ni][3] + bb.y;
            if (EPI == 1) {
                float2 r0 = *reinterpret_cast<const float2*>(Res + (size_t)row * N + col);
                float2 r1 = *reinterpret_cast<const float2*>(Res + (size_t)(row + 8) * N + col);
                v00 += r0.x; v01 += r0.y; v10 += r1.x; v11 += r1.y;
            }
            if (EPI <= 1) {
                float2 o0 = make_float2(v00, v01);
                float2 o1 = make_float2(v10, v11);
                *reinterpret_cast<float2*>(Cf + (size_t)row * N + col) = o0;
                *reinterpret_cast<float2*>(Cf + (size_t)(row + 8) * N + col) = o1;
            } else {
                v00 = gelu_tanh(v00); v01 = gelu_tanh(v01);
                v10 = gelu_tanh(v10); v11 = gelu_tanh(v11);
                BF16 h0[2], l0[2], h1[2], l1[2];
                split1(v00, h0[0], l0[0]); split1(v01, h0[1], l0[1]);
                split1(v10, h1[0], l1[0]); split1(v11, h1[1], l1[1]);
                *reinterpret_cast<uint32_t*>(Ch + (size_t)row * N + col) =
                    *reinterpret_cast<uint32_t*>(h0);
                *reinterpret_cast<uint32_t*>(Cl + (size_t)row * N + col) =
                    *reinterpret_cast<uint32_t*>(l0);
                *reinterpret_cast<uint32_t*>(Ch + (size_t)(row + 8) * N + col) =
                    *reinterpret_cast<uint32_t*>(h1);
                *reinterpret_cast<uint32_t*>(Cl + (size_t)(row + 8) * N + col) =
                    *reinterpret_cast<uint32_t*>(l1);
            }
        }
    }
}

// ---------------------------------------------------------------------------
// Flash attention (fp32, causal): 64x64 tiles, online softmax.
// Writes bf16 hi/lo output for the W_o GEMM. Dynamic SMEM = 67584 bytes.
// ---------------------------------------------------------------------------
__global__ void __launch_bounds__(256) attn_kernel(
    const float* __restrict__ qkv, BF16* __restrict__ y_hi,
    BF16* __restrict__ y_lo)
{
    const int T = 2048, C3 = 3072;
    extern __shared__ float sm[];
    float* Qs   = sm;
    float* KsT  = Qs  + 64 * 64;
    float* Vs   = KsT + 64 * 68;
    float* Ss   = Vs  + 64 * 64;
    float* m_s  = Ss  + 64 * 65;
    float* l_s  = m_s + 64;
    float* al_s = l_s + 64;

    const int q0 = blockIdx.x * 64;
    const int bh = blockIdx.y;
    const int bb = bh >> 4, hh = bh & 15;
    const float* qbase = qkv + (size_t)bb * T * C3 + hh * 64;
    const float* kbase = qbase + 1024;
    const float* vbase = qbase + 2048;

    const int tid = threadIdx.x;
    const int tx = tid & 15, ty = tid >> 4;
    const int r0 = ty * 4, c0 = tx * 4;

    #pragma unroll
    for (int i = 0; i < 4; i++) {
        const int v = tid + i * 256;
        const int r = v >> 4, d4 = (v & 15) * 4;
        float4 q = *reinterpret_cast<const float4*>(qbase + (size_t)(q0 + r) * C3 + d4);
        q.x *= 0.125f; q.y *= 0.125f; q.z *= 0.125f; q.w *= 0.125f;
        *reinterpret_cast<float4*>(Qs + r * 64 + d4) = q;
    }
    if (tid < 64) { m_s[tid] = -1e30f; l_s[tid] = 0.f; }

    float o[4][4];
    #pragma unroll
    for (int i = 0; i < 4; i++)
        #pragma unroll
        for (int j = 0; j < 4; j++) o[i][j] = 0.f;

    const int ntiles = (q0 >> 6) + 1;
    for (int jt = 0; jt < ntiles; jt++) {
        const int j0 = jt * 64;
        __syncthreads();
        #pragma unroll
        for (int i = 0; i < 4; i++) {
            const int v = tid + i * 256;
            const int jr = v & 63, d4 = (v >> 6) * 4;
            float4 kk = *reinterpret_cast<const float4*>(kbase + (size_t)(j0 + jr) * C3 + d4);
            KsT[(d4 + 0) * 68 + jr] = kk.x;
            KsT[(d4 + 1) * 68 + jr] = kk.y;
            KsT[(d4 + 2) * 68 + jr] = kk.z;
            KsT[(d4 + 3) * 68 + jr] = kk.w;
        }
        #pragma unroll
        for (int i = 0; i < 4; i++) {
            const int v = tid + i * 256;
            const int jr = v >> 4, d4 = (v & 15) * 4;
            float4 vv = *reinterpret_cast<const float4*>(vbase + (size_t)(j0 + jr) * C3 + d4);
            *reinterpret_cast<float4*>(Vs + jr * 64 + d4) = vv;
        }
        __syncthreads();

        float s4[4][4];
        #pragma unroll
        for (int i = 0; i < 4; i++)
            #pragma unroll
            for (int j = 0; j < 4; j++) s4[i][j] = 0.f;
        #pragma unroll 8
        for (int d = 0; d < 64; d++) {
            const float4 kv = *reinterpret_cast<const float4*>(KsT + d * 68 + c0);
            const float q0v = Qs[(r0 + 0) * 64 + d];
            const float q1v = Qs[(r0 + 1) * 64 + d];
            const float q2v = Qs[(r0 + 2) * 64 + d];
            const float q3v = Qs[(r0 + 3) * 64 + d];
            s4[0][0] = fmaf(q0v, kv.x, s4[0][0]); s4[0][1] = fmaf(q0v, kv.y, s4[0][1]);
            s4[0][2] = fmaf(q0v, kv.z, s4[0][2]); s4[0][3] = fmaf(q0v, kv.w, s4[0][3]);
            s4[1][0] = fmaf(q1v, kv.x, s4[1][0]); s4[1][1] = fmaf(q1v, kv.y, s4[1][1]);
            s4[1][2] = fmaf(q1v, kv.z, s4[1][2]); s4[1][3] = fmaf(q1v, kv.w, s4[1][3]);
            s4[2][0] = fmaf(q2v, kv.x, s4[2][0]); s4[2][1] = fmaf(q2v, kv.y, s4[2][1]);
            s4[2][2] = fmaf(q2v, kv.z, s4[2][2]); s4[2][3] = fmaf(q2v, kv.w, s4[2][3]);
            s4[3][0] = fmaf(q3v, kv.x, s4[3][0]); s4[3][1] = fmaf(q3v, kv.y, s4[3][1]);
            s4[3][2] = fmaf(q3v, kv.z, s4[3][2]); s4[3][3] = fmaf(q3v, kv.w, s4[3][3]);
        }
        if (j0 == q0) {
            #pragma unroll
            for (int rr = 0; rr < 4; rr++)
                #pragma unroll
                for (int cc = 0; cc < 4; cc++)
                    if (c0 + cc > r0 + rr) s4[rr][cc] = -1e30f;
        }
        #pragma unroll
        for (int rr = 0; rr < 4; rr++)
            #pragma unroll
            for (int cc = 0; cc < 4; cc++)
                Ss[(r0 + rr) * 65 + c0 + cc] = s4[rr][cc];
        __syncthreads();

        {
            const int row = tid >> 2, part = tid & 3;
            float* srow = Ss + row * 65 + part * 16;
            float mx = -1e30f;
            #pragma unroll
            for (int j = 0; j < 16; j++) mx = fmaxf(mx, srow[j]);
            mx = fmaxf(mx, __shfl_xor_sync(0xffffffffu, mx, 1));
            mx = fmaxf(mx, __shfl_xor_sync(0xffffffffu, mx, 2));
            const float m_old = m_s[row];
            const float m_new = fmaxf(m_old, mx);
            float sum = 0.f;
            #pragma unroll
            for (int j = 0; j < 16; j++) {
                const float p = __expf(srow[j] - m_new);
                srow[j] = p;
                sum += p;
            }
            sum += __shfl_xor_sync(0xffffffffu, sum, 1);
            sum += __shfl_xor_sync(0xffffffffu, sum, 2);
            if (part == 0) {
                const float alpha = __expf(m_old - m_new);
                al_s[row] = alpha;
                m_s[row]  = m_new;
                l_s[row]  = l_s[row] * alpha + sum;
            }
        }
        __syncthreads();

        const float a0 = al_s[r0 + 0], a1 = al_s[r0 + 1];
        const float a2 = al_s[r0 + 2], a3 = al_s[r0 + 3];
        #pragma unroll
        for (int cc = 0; cc < 4; cc++) {
            o[0][cc] *= a0; o[1][cc] *= a1; o[2][cc] *= a2; o[3][cc] *= a3;
        }
        #pragma unroll 8
        for (int j = 0; j < 64; j++) {
            const float4 vv = *reinterpret_cast<const float4*>(Vs + j * 64 + c0);
            const float p0 = Ss[(r0 + 0) * 65 + j];
            const float p1 = Ss[(r0 + 1) * 65 + j];
            const float p2 = Ss[(r0 + 2) * 65 + j];
            const float p3 = Ss[(r0 + 3) * 65 + j];
            o[0][0] = fmaf(p0, vv.x, o[0][0]); o[0][1] = fmaf(p0, vv.y, o[0][1]);
            o[0][2] = fmaf(p0, vv.z, o[0][2]); o[0][3] = fmaf(p0, vv.w, o[0][3]);
            o[1][0] = fmaf(p1, vv.x, o[1][0]); o[1][1] = fmaf(p1, vv.y, o[1][1]);
            o[1][2] = fmaf(p1, vv.z, o[1][2]); o[1][3] = fmaf(p1, vv.w, o[1][3]);
            o[2][0] = fmaf(p2, vv.x, o[2][0]); o[2][1] = fmaf(p2, vv.y, o[2][1]);
            o[2][2] = fmaf(p2, vv.z, o[2][2]); o[2][3] = fmaf(p2, vv.w, o[2][3]);
            o[3][0] = fmaf(p3, vv.x, o[3][0]); o[3][1] = fmaf(p3, vv.y, o[3][1]);
            o[3][2] = fmaf(p3, vv.z, o[3][2]); o[3][3] = fmaf(p3, vv.w, o[3][3]);
        }
    }

    #pragma unroll
    for (int rr = 0; rr < 4; rr++) {
        const float inv = 1.0f / l_s[r0 + rr];
        BF16 hv[4], lv[4];
        split1(o[rr][0] * inv, hv[0], lv[0]);
        split1(o[rr][1] * inv, hv[1], lv[1]);
        split1(o[rr][2] * inv, hv[2], lv[2]);
        split1(o[rr][3] * inv, hv[3], lv[3]);
        const size_t idx = ((size_t)bb * T + q0 + r0 + rr) * 1024 + hh * 64 + c0;
        *reinterpret_cast<uint2*>(y_hi + idx) = *reinterpret_cast<uint2*>(hv);
        *reinterpret_cast<uint2*>(y_lo + idx) = *reinterpret_cast<uint2*>(lv);
    }
}

// ---------------------------------------------------------------------------
// Launch
// ---------------------------------------------------------------------------
extern "C" void kernel_launch(void* const* d_in, const int* in_sizes, int n_in,
                              void* d_out, int out_size)
{
    const float* x      = (const float*)d_in[0];
    const float* ln1_g  = (const float*)d_in[1];
    const float* ln1_b  = (const float*)d_in[2];
    const float* W_attn = (const float*)d_in[3];
    const float* b_attn = (const float*)d_in[4];
    const float* W_o    = (const float*)d_in[5];
    const float* b_o    = (const float*)d_in[6];
    const float* ln2_g  = (const float*)d_in[7];
    const float* ln2_b  = (const float*)d_in[8];
    const float* W_fc   = (const float*)d_in[9];
    const float* b_fc   = (const float*)d_in[10];
    const float* W_fc2  = (const float*)d_in[11];
    const float* b_fc2  = (const float*)d_in[12];
    float* out = (float*)d_out;

    float *qkv, *x1;
    BF16 *h_hi, *h_lo, *y_hi, *y_lo, *fc_hi, *fc_lo;
    BF16 *wq_hi, *wq_lo, *wo_hi, *wo_lo, *wf_hi, *wf_lo, *w2_hi, *w2_lo;
    cudaGetSymbolAddress((void**)&qkv,   g_qkv);
    cudaGetSymbolAddress((void**)&x1,    g_x1);
    cudaGetSymbolAddress((void**)&h_hi,  g_h_hi);
    cudaGetSymbolAddress((void**)&h_lo,  g_h_lo);
    cudaGetSymbolAddress((void**)&y_hi,  g_y_hi);
    cudaGetSymbolAddress((void**)&y_lo,  g_y_lo);
    cudaGetSymbolAddress((void**)&fc_hi, g_fc_hi);
    cudaGetSymbolAddress((void**)&fc_lo, g_fc_lo);
    cudaGetSymbolAddress((void**)&wq_hi, g_wqkv_hi);
    cudaGetSymbolAddress((void**)&wq_lo, g_wqkv_lo);
    cudaGetSymbolAddress((void**)&wo_hi, g_wo_hi);
    cudaGetSymbolAddress((void**)&wo_lo, g_wo_lo);
    cudaGetSymbolAddress((void**)&wf_hi, g_wfc_hi);
    cudaGetSymbolAddress((void**)&wf_lo, g_wfc_lo);
    cudaGetSymbolAddress((void**)&w2_hi, g_wfc2_hi);
    cudaGetSymbolAddress((void**)&w2_lo, g_wfc2_lo);

    const int GEMM_SMEM = SM_ELEMS * 2;   // 75776 bytes
    const int ATTN_SMEM = 67584;
    cudaFuncSetAttribute(hgemm_kernel<0>,
                         cudaFuncAttributeMaxDynamicSharedMemorySize, GEMM_SMEM);
    cudaFuncSetAttribute(hgemm_kernel<1>,
                         cudaFuncAttributeMaxDynamicSharedMemorySize, GEMM_SMEM);
    cudaFuncSetAttribute(hgemm_kernel<2>,
                         cudaFuncAttributeMaxDynamicSharedMemorySize, GEMM_SMEM);
    cudaFuncSetAttribute(attn_kernel,
                         cudaFuncAttributeMaxDynamicSharedMemorySize, ATTN_SMEM);

    const int M = 4096;

    // 0. split weights to bf16 hi/lo
    split_kernel<<<(1024 * 3072 / 4 + 255) / 256, 256>>>(W_attn, wq_hi, wq_lo, 1024 * 3072 / 4);
    split_kernel<<<(1024 * 1024 / 4 + 255) / 256, 256>>>(W_o,    wo_hi, wo_lo, 1024 * 1024 / 4);
    split_kernel<<<(1024 * 4096 / 4 + 255) / 256, 256>>>(W_fc,   wf_hi, wf_lo, 1024 * 4096 / 4);
    split_kernel<<<(4096 * 1024 / 4 + 255) / 256, 256>>>(W_fc2,  w2_hi, w2_lo, 4096 * 1024 / 4);

    // 1. LN1 -> h (bf16 hi/lo)
    ln_kernel<<<M, 256>>>(x, ln1_g, ln1_b, h_hi, h_lo);
    // 2. QKV = h @ W_attn + b_attn  (fp32 out)
    hgemm_kernel<0><<<dim3(3072 / 128, M / 128), 256, GEMM_SMEM>>>(
        h_hi, h_lo, wq_hi, wq_lo, b_attn, nullptr, qkv, nullptr, nullptr,
        M, 3072, 1024);
    // 3. attention -> y (bf16 hi/lo)
    attn_kernel<<<dim3(32, 32), 256, ATTN_SMEM>>>(qkv, y_hi, y_lo);
    // 4. x1 = x + y @ W_o + b_o
    hgemm_kernel<1><<<dim3(1024 / 128, M / 128), 256, GEMM_SMEM>>>(
        y_hi, y_lo, wo_hi, wo_lo, b_o, x, x1, nullptr, nullptr,
        M, 1024, 1024);
    // 5. LN2 -> h (bf16 hi/lo)
    ln_kernel<<<M, 256>>>(x1, ln2_g, ln2_b, h_hi, h_lo);
    // 6. fc = gelu(h @ W_fc + b_fc)  (bf16 hi/lo out)
    hgemm_kernel<2><<<dim3(4096 / 128, M / 128), 256, GEMM_SMEM>>>(
        h_hi, h_lo, wf_hi, wf_lo, b_fc, nullptr, nullptr, fc_hi, fc_lo,
        M, 4096, 1024);
    // 7. out = x1 + fc @ W_fc2 + b_fc2
    hgemm_kernel<1><<<dim3(1024 / 128, M / 128), 256, GEMM_SMEM>>>(
        fc_hi, fc_lo, w2_hi, w2_lo, b_fc2, x1, out, nullptr, nullptr,
        M, 1024, 4096);
}